// round 3
// baseline (speedup 1.0000x reference)
#include <cuda_runtime.h>

#define KC 1024
#define DC 64
#define NV 131072
#define TM 128      // rows per block
#define TKC 128     // codes per chunk

// scratch (allocation-free: __device__ globals). 16B-aligned for vector access.
__device__ __align__(16) float g_esq[KC];
__device__ __align__(16) float g_counts[KC];
__device__ __align__(16) float g_sums[KC * DC];
__device__ float g_loss[1];
__device__ __align__(16) float g_csa[KC];

__device__ __forceinline__ void fma2(unsigned long long &acc, unsigned long long a,
                                     unsigned long long b) {
    asm("fma.rn.f32x2 %0, %1, %2, %0;" : "+l"(acc) : "l"(a), "l"(b));
}
__device__ __forceinline__ unsigned long long pack2(float lo, float hi) {
    unsigned long long r;
    asm("mov.b64 %0, {%1, %2};" : "=l"(r) : "f"(lo), "f"(hi));
    return r;
}
__device__ __forceinline__ float2 unpack2(unsigned long long v) {
    float2 r;
    asm("mov.b64 {%0, %1}, %2;" : "=f"(r.x), "=f"(r.y) : "l"(v));
    return r;
}

// ---------------- prep kernels ----------------
__global__ void vq_zero() {
    int i = blockIdx.x * blockDim.x + threadIdx.x;
    if (i < KC * DC / 4) {
        ((float4*)g_sums)[i] = make_float4(0.f, 0.f, 0.f, 0.f);
    } else if (i < KC * DC / 4 + KC) {
        g_counts[i - KC * DC / 4] = 0.f;
    } else if (i == KC * DC / 4 + KC) {
        g_loss[0] = 0.f;
    }
}

__global__ void vq_esq(const float* __restrict__ E) {
    int k = blockIdx.x * blockDim.x + threadIdx.x;
    if (k < KC) {
        const float4* r = (const float4*)(E + (size_t)k * DC);
        float s = 0.f;
#pragma unroll
        for (int q = 0; q < DC / 4; q++) {
            float4 v = r[q];
            s = fmaf(v.x, v.x, s); s = fmaf(v.y, v.y, s);
            s = fmaf(v.z, v.z, s); s = fmaf(v.w, v.w, s);
        }
        g_esq[k] = s;
    }
}

// ---------------- main kernel ----------------
// smem (floats):
//   Xs   [64][132]  d-major, pitch 132 -> 16B-aligned rows for LDS.128   (8448)
//   Es2  [128][65]  8-byte (e,e) dup entries, k-major, pitch 65 entries  (16640)
//   esqs [1024]                                                          (1024)
//   xsq  [128]                                                           (128)
#define XS_PITCH 132
#define ES_PITCH8 65
#define SMEM_FLOATS (DC * XS_PITCH + TKC * ES_PITCH8 * 2 + KC + TM)

extern "C" __global__ void __launch_bounds__(256, 2)
vq_main(const float* __restrict__ X, const float* __restrict__ E,
        float* __restrict__ oZ, float* __restrict__ oArg, float* __restrict__ oMin) {
    extern __shared__ float smem[];
    float* Xs = smem;                                // DC * XS_PITCH
    float* Es2 = smem + DC * XS_PITCH;               // TKC * ES_PITCH8 * 2
    float* esqs = Es2 + TKC * ES_PITCH8 * 2;         // KC
    float* xsq = esqs + KC;                          // TM
    unsigned long long* E8 = (unsigned long long*)Es2;

    int tid = threadIdx.x;
    int tx = tid & 15;        // code group (codes tx + 16*j)
    int ty = tid >> 4;        // row group (rows ty*8 .. ty*8+7)

    // preload e squared norms (kills per-chunk LDG stalls in epilogue)
#pragma unroll
    for (int i = tid; i < KC; i += 256) esqs[i] = g_esq[i];

    // load X tile (coalesced gmem read, transposed store)
    const float* Xg = X + (size_t)blockIdx.x * TM * DC;
#pragma unroll
    for (int i = tid; i < TM * DC; i += 256) {
        int r = i >> 6, d = i & 63;
        Xs[d * XS_PITCH + r] = Xg[i];
    }
    __syncthreads();

    if (tid < TM) {
        float s = 0.f;
#pragma unroll 8
        for (int d = 0; d < DC; d++) {
            float v = Xs[d * XS_PITCH + tid];
            s = fmaf(v, v, s);
        }
        xsq[tid] = s;
    }

    float best[8];
    int bidx[8];
#pragma unroll
    for (int l = 0; l < 8; l++) { best[l] = 3.4e38f; bidx[l] = 0; }

    for (int ch = 0; ch < KC / TKC; ch++) {
        __syncthreads();   // previous chunk's E8 reads done (and xsq writes on first iter)
        const float* Eg = E + (size_t)ch * TKC * DC;
        // store E chunk as duplicated (e,e) 8B entries, k-major: coalesced gmem read,
        // stores hit banks (2k+2d)%32 -> 2-way max; loads in main loop conflict-free.
#pragma unroll
        for (int i = tid; i < TKC * DC; i += 256) {
            int k = i >> 6, d = i & 63;
            float v = Eg[i];
            E8[k * ES_PITCH8 + d] = pack2(v, v);
        }
        __syncthreads();

        unsigned long long acc[4][8];
#pragma unroll
        for (int rp = 0; rp < 4; rp++)
#pragma unroll
            for (int j = 0; j < 8; j++) acc[rp][j] = 0ull;

#pragma unroll 4
        for (int d = 0; d < DC; d++) {
            const float* xr = Xs + d * XS_PITCH + ty * 8;
            ulonglong2 xq0 = *(const ulonglong2*)(xr);       // rows 0..3 (LDS.128)
            ulonglong2 xq1 = *(const ulonglong2*)(xr + 4);   // rows 4..7 (LDS.128)
            const unsigned long long* er = E8 + tx * ES_PITCH8 + d;
#pragma unroll
            for (int j = 0; j < 8; j++) {
                unsigned long long ed = er[16 * ES_PITCH8 * j];   // (e,e) dup, LDS.64
                fma2(acc[0][j], xq0.x, ed);
                fma2(acc[1][j], xq0.y, ed);
                fma2(acc[2][j], xq1.x, ed);
                fma2(acc[3][j], xq1.y, ed);
            }
        }

        // chunk epilogue: dist-without-xsq = esq - 2*dot; strict < keeps earliest index
#pragma unroll
        for (int j = 0; j < 8; j++) {
            int c = ch * TKC + tx + 16 * j;
            float es = esqs[c];
#pragma unroll
            for (int rp = 0; rp < 4; rp++) {
                float2 dd = unpack2(acc[rp][j]);
                float s0 = fmaf(-2.f, dd.x, es);
                float s1 = fmaf(-2.f, dd.y, es);
                if (s0 < best[2 * rp])     { best[2 * rp] = s0;     bidx[2 * rp] = c; }
                if (s1 < best[2 * rp + 1]) { best[2 * rp + 1] = s1; bidx[2 * rp + 1] = c; }
            }
        }
    }
    __syncthreads();

    // cross-thread argmin reduction (reuse Es2 space), pitch 17 = conflict-free scan
    float* red_d = Es2;
    int* red_i = (int*)(Es2 + TM * 17);
#pragma unroll
    for (int l = 0; l < 8; l++) {
        int row = ty * 8 + l;
        red_d[row * 17 + tx] = best[l];
        red_i[row * 17 + tx] = bidx[l];
    }
    __syncthreads();

    if (tid < TM) {
        int row = tid;
        float bd = red_d[row * 17];
        int bi = red_i[row * 17];
#pragma unroll
        for (int t = 1; t < 16; t++) {
            float v = red_d[row * 17 + t];
            int ii = red_i[row * 17 + t];
            if (v < bd || (v == bd && ii < bi)) { bd = v; bi = ii; }
        }
        size_t gr = (size_t)blockIdx.x * TM + row;
        oMin[gr] = xsq[row] + bd;
        oArg[gr] = (float)bi;

        const float4* Er = (const float4*)(E + (size_t)bi * DC);
        float4* Zr = (float4*)(oZ + gr * DC);
        float lsum = 0.f;
        atomicAdd(&g_counts[bi], 1.0f);
        float* srow = &g_sums[bi * DC];
#pragma unroll 4
        for (int q = 0; q < DC / 4; q++) {
            float4 e4 = Er[q];
            float x0 = Xs[(4 * q + 0) * XS_PITCH + row];
            float x1 = Xs[(4 * q + 1) * XS_PITCH + row];
            float x2 = Xs[(4 * q + 2) * XS_PITCH + row];
            float x3 = Xs[(4 * q + 3) * XS_PITCH + row];
            float d0 = e4.x - x0, d1 = e4.y - x1, d2 = e4.z - x2, d3 = e4.w - x3;
            float4 z;
            z.x = x0 + d0; z.y = x1 + d1; z.z = x2 + d2; z.w = x3 + d3;  // X + (Zraw - X)
            Zr[q] = z;
            lsum = fmaf(d0, d0, lsum); lsum = fmaf(d1, d1, lsum);
            lsum = fmaf(d2, d2, lsum); lsum = fmaf(d3, d3, lsum);
            atomicAdd(srow + 4 * q + 0, x0);
            atomicAdd(srow + 4 * q + 1, x1);
            atomicAdd(srow + 4 * q + 2, x2);
            atomicAdd(srow + 4 * q + 3, x3);
        }
#pragma unroll
        for (int o = 16; o > 0; o >>= 1) lsum += __shfl_xor_sync(0xffffffffu, lsum, o);
        if ((tid & 31) == 0) atomicAdd(g_loss, lsum);
    }
}

// ---------------- finalize (split: tiny scalar part + parallel KxD part) ----------------
__global__ void vq_fin1(const float* __restrict__ cs_in,
                        float* __restrict__ oCs, float* __restrict__ oLoss) {
    __shared__ float wsum[32];
    __shared__ float Ssh;
    int k = threadIdx.x;
    const float G = 0.99f;
    const float OMG = (float)(1.0 - 0.99);   // match reference (1.0 - GAMMA)
    float c = G * cs_in[k] + OMG * g_counts[k];

    float s = c;
#pragma unroll
    for (int o = 16; o > 0; o >>= 1) s += __shfl_xor_sync(0xffffffffu, s, o);
    if ((k & 31) == 0) wsum[k >> 5] = s;
    __syncthreads();
    if (k < 32) {
        float t = wsum[k];
#pragma unroll
        for (int o = 16; o > 0; o >>= 1) t += __shfl_xor_sync(0xffffffffu, t, o);
        if (k == 0) Ssh = t;
    }
    __syncthreads();
    float S = Ssh;

    float csa = (c + 1e-9f) / (1.0f + (float)(1e-9 * 1024.0) / S);
    oCs[k] = csa;
    g_csa[k] = csa;
    if (k == 0) oLoss[0] = 0.25f * g_loss[0] / (float)NV;
}

// NOTE: oEn/oMa are offset by +1 float in d_out (loss scalar) -> NOT 16B aligned.
// Vector loads only from aligned sources; scalar stores to outputs.
__global__ void vq_fin2(const float* __restrict__ mavg,
                        float* __restrict__ oEn, float* __restrict__ oMa) {
    const float G = 0.99f;
    const float OMG = (float)(1.0 - 0.99);
    int i4 = blockIdx.x * blockDim.x + threadIdx.x;  // float4 index over K*D/4
    float4 mv = ((const float4*)mavg)[i4];
    float4 sv = ((const float4*)g_sums)[i4];
    float csa = g_csa[i4 >> 4];                      // 16 float4 per code row
    int b = i4 * 4;
    float m0 = G * mv.x + OMG * sv.x;
    float m1 = G * mv.y + OMG * sv.y;
    float m2 = G * mv.z + OMG * sv.z;
    float m3 = G * mv.w + OMG * sv.w;
    oMa[b + 0] = m0;  oEn[b + 0] = m0 / csa;
    oMa[b + 1] = m1;  oEn[b + 1] = m1 / csa;
    oMa[b + 2] = m2;  oEn[b + 2] = m2 / csa;
    oMa[b + 3] = m3;  oEn[b + 3] = m3 / csa;
}

// ---------------- launch ----------------
extern "C" void kernel_launch(void* const* d_in, const int* in_sizes, int n_in,
                              void* d_out, int out_size) {
    const float* X  = (const float*)d_in[0];
    const float* E  = (const float*)d_in[1];
    const float* cs = (const float*)d_in[2];
    const float* ma = (const float*)d_in[3];

    float* o = (float*)d_out;
    // output layout: Z[N*D], loss[1], argmins[N], min_dist[N], E_new[K*D], cs[K], ma[K*D]
    float* oZ    = o;
    float* oLoss = o + (size_t)NV * DC;
    float* oArg  = oLoss + 1;
    float* oMin  = oArg + NV;
    float* oEn   = oMin + NV;
    float* oCs   = oEn + (size_t)KC * DC;
    float* oMa   = oCs + KC;

    int smem = SMEM_FLOATS * 4;
    cudaFuncSetAttribute(vq_main, cudaFuncAttributeMaxDynamicSharedMemorySize, smem);

    vq_zero<<<(KC * DC / 4 + KC + 1 + 255) / 256, 256>>>();
    vq_esq<<<(KC + 255) / 256, 256>>>(E);
    vq_main<<<NV / TM, 256, smem>>>(X, E, oZ, oArg, oMin);
    vq_fin1<<<1, KC>>>(cs, oCs, oLoss);
    vq_fin2<<<KC * DC / 4 / 256, 256>>>(ma, oEn, oMa);
}

// round 4
// speedup vs baseline: 1.7214x; 1.7214x over previous
#include <cuda_runtime.h>

#define KC 1024
#define DC 64
#define NV 131072
#define TM 128      // rows per block
#define TKC 128     // codes per chunk

// scratch (allocation-free: __device__ globals). 16B-aligned for vector access.
__device__ __align__(16) float g_esq[KC];
__device__ __align__(16) float g_counts[KC];
__device__ __align__(16) float g_sums[KC * DC];
__device__ float g_loss[1];
__device__ __align__(16) float g_csa[KC];

__device__ __forceinline__ void fma2(unsigned long long &acc, unsigned long long a,
                                     unsigned long long b) {
    asm("fma.rn.f32x2 %0, %1, %2, %0;" : "+l"(acc) : "l"(a), "l"(b));
}
__device__ __forceinline__ unsigned long long pack2(float lo, float hi) {
    unsigned long long r;
    asm("mov.b64 %0, {%1, %2};" : "=l"(r) : "f"(lo), "f"(hi));
    return r;
}
__device__ __forceinline__ float2 unpack2(unsigned long long v) {
    float2 r;
    asm("mov.b64 {%0, %1}, %2;" : "=f"(r.x), "=f"(r.y) : "l"(v));
    return r;
}

// ---------------- prep kernels ----------------
__global__ void vq_zero() {
    int i = blockIdx.x * blockDim.x + threadIdx.x;
    if (i < KC * DC / 4) {
        ((float4*)g_sums)[i] = make_float4(0.f, 0.f, 0.f, 0.f);
    } else if (i < KC * DC / 4 + KC) {
        g_counts[i - KC * DC / 4] = 0.f;
    } else if (i == KC * DC / 4 + KC) {
        g_loss[0] = 0.f;
    }
}

__global__ void vq_esq(const float* __restrict__ E) {
    int k = blockIdx.x * blockDim.x + threadIdx.x;
    if (k < KC) {
        const float4* r = (const float4*)(E + (size_t)k * DC);
        float s = 0.f;
#pragma unroll
        for (int q = 0; q < DC / 4; q++) {
            float4 v = r[q];
            s = fmaf(v.x, v.x, s); s = fmaf(v.y, v.y, s);
            s = fmaf(v.z, v.z, s); s = fmaf(v.w, v.w, s);
        }
        g_esq[k] = s;
    }
}

// ---------------- main kernel (R1 version — measured ~445us; R3 variant regressed) ----
// smem: Xs[64][130] d-major (rows contiguous, pitch 130 -> LDS.64 aligned, conflict-free),
//       Es[64][129] d-major (scalar loads, conflict-free), xsq[128]
#define XS_PITCH 130
#define ES_PITCH 129
#define SMEM_FLOATS (DC * XS_PITCH + DC * ES_PITCH + TM)

extern "C" __global__ void __launch_bounds__(256, 2)
vq_main(const float* __restrict__ X, const float* __restrict__ E,
        float* __restrict__ oZ, float* __restrict__ oArg, float* __restrict__ oMin) {
    extern __shared__ float smem[];
    float* Xs = smem;                       // DC * XS_PITCH
    float* Es = smem + DC * XS_PITCH;       // DC * ES_PITCH
    float* xsq = Es + DC * ES_PITCH;        // TM

    int tid = threadIdx.x;
    int tx = tid & 15;        // code group (codes tx + 16*j)
    int ty = tid >> 4;        // row group (rows ty*8 .. ty*8+7)

    // load X tile (coalesced gmem read, transposed store; bank = (2d+row)%32, 2-way max)
    const float* Xg = X + (size_t)blockIdx.x * TM * DC;
#pragma unroll
    for (int i = tid; i < TM * DC; i += 256) {
        int r = i >> 6, d = i & 63;
        Xs[d * XS_PITCH + r] = Xg[i];
    }
    __syncthreads();

    if (tid < TM) {
        float s = 0.f;
#pragma unroll 8
        for (int d = 0; d < DC; d++) {
            float v = Xs[d * XS_PITCH + tid];
            s = fmaf(v, v, s);
        }
        xsq[tid] = s;
    }

    float best[8];
    int bidx[8];
#pragma unroll
    for (int l = 0; l < 8; l++) { best[l] = 3.4e38f; bidx[l] = 0; }

    for (int ch = 0; ch < KC / TKC; ch++) {
        __syncthreads();   // previous chunk's Es reads done (and xsq writes on first iter)
        const float* Eg = E + (size_t)ch * TKC * DC;
#pragma unroll
        for (int i = tid; i < TKC * DC; i += 256) {
            int k = i >> 6, d = i & 63;
            Es[d * ES_PITCH + k] = Eg[i];
        }
        __syncthreads();

        unsigned long long acc[4][8];
#pragma unroll
        for (int rp = 0; rp < 4; rp++)
#pragma unroll
            for (int j = 0; j < 8; j++) acc[rp][j] = 0ull;

#pragma unroll 4
        for (int d = 0; d < DC; d++) {
            const float* xr = Xs + d * XS_PITCH + ty * 8;
            unsigned long long xp0 = *(const unsigned long long*)(xr);
            unsigned long long xp1 = *(const unsigned long long*)(xr + 2);
            unsigned long long xp2 = *(const unsigned long long*)(xr + 4);
            unsigned long long xp3 = *(const unsigned long long*)(xr + 6);
            const float* er = Es + d * ES_PITCH + tx;
#pragma unroll
            for (int j = 0; j < 8; j++) {
                float e = er[16 * j];
                unsigned long long ed = pack2(e, e);
                fma2(acc[0][j], xp0, ed);
                fma2(acc[1][j], xp1, ed);
                fma2(acc[2][j], xp2, ed);
                fma2(acc[3][j], xp3, ed);
            }
        }

        // chunk epilogue: dist-without-xsq = esq - 2*dot; strict < keeps earliest index
#pragma unroll
        for (int j = 0; j < 8; j++) {
            int c = ch * TKC + tx + 16 * j;
            float es = g_esq[c];
#pragma unroll
            for (int rp = 0; rp < 4; rp++) {
                float2 dd = unpack2(acc[rp][j]);
                float s0 = fmaf(-2.f, dd.x, es);
                float s1 = fmaf(-2.f, dd.y, es);
                if (s0 < best[2 * rp])     { best[2 * rp] = s0;     bidx[2 * rp] = c; }
                if (s1 < best[2 * rp + 1]) { best[2 * rp + 1] = s1; bidx[2 * rp + 1] = c; }
            }
        }
    }
    __syncthreads();

    // cross-thread argmin reduction (reuse Es space), pitch 17 = conflict-free scan
    float* red_d = Es;
    int* red_i = (int*)(Es + TM * 17);
#pragma unroll
    for (int l = 0; l < 8; l++) {
        int row = ty * 8 + l;
        red_d[row * 17 + tx] = best[l];
        red_i[row * 17 + tx] = bidx[l];
    }
    __syncthreads();

    if (tid < TM) {
        int row = tid;
        float bd = red_d[row * 17];
        int bi = red_i[row * 17];
#pragma unroll
        for (int t = 1; t < 16; t++) {
            float v = red_d[row * 17 + t];
            int ii = red_i[row * 17 + t];
            if (v < bd || (v == bd && ii < bi)) { bd = v; bi = ii; }
        }
        size_t gr = (size_t)blockIdx.x * TM + row;
        oMin[gr] = xsq[row] + bd;
        oArg[gr] = (float)bi;

        const float4* Er = (const float4*)(E + (size_t)bi * DC);
        float4* Zr = (float4*)(oZ + gr * DC);
        float lsum = 0.f;
        atomicAdd(&g_counts[bi], 1.0f);
        float* srow = &g_sums[bi * DC];
#pragma unroll 4
        for (int q = 0; q < DC / 4; q++) {
            float4 e4 = Er[q];
            float x0 = Xs[(4 * q + 0) * XS_PITCH + row];
            float x1 = Xs[(4 * q + 1) * XS_PITCH + row];
            float x2 = Xs[(4 * q + 2) * XS_PITCH + row];
            float x3 = Xs[(4 * q + 3) * XS_PITCH + row];
            float d0 = e4.x - x0, d1 = e4.y - x1, d2 = e4.z - x2, d3 = e4.w - x3;
            float4 z;
            z.x = x0 + d0; z.y = x1 + d1; z.z = x2 + d2; z.w = x3 + d3;  // X + (Zraw - X)
            Zr[q] = z;
            lsum = fmaf(d0, d0, lsum); lsum = fmaf(d1, d1, lsum);
            lsum = fmaf(d2, d2, lsum); lsum = fmaf(d3, d3, lsum);
            atomicAdd(srow + 4 * q + 0, x0);
            atomicAdd(srow + 4 * q + 1, x1);
            atomicAdd(srow + 4 * q + 2, x2);
            atomicAdd(srow + 4 * q + 3, x3);
        }
#pragma unroll
        for (int o = 16; o > 0; o >>= 1) lsum += __shfl_xor_sync(0xffffffffu, lsum, o);
        if ((tid & 31) == 0) atomicAdd(g_loss, lsum);
    }
}

// ---------------- finalize (split: tiny scalar part + parallel KxD part) ----------------
__global__ void vq_fin1(const float* __restrict__ cs_in,
                        float* __restrict__ oCs, float* __restrict__ oLoss) {
    __shared__ float wsum[32];
    __shared__ float Ssh;
    int k = threadIdx.x;
    const float G = 0.99f;
    const float OMG = (float)(1.0 - 0.99);   // match reference (1.0 - GAMMA)
    float c = G * cs_in[k] + OMG * g_counts[k];

    float s = c;
#pragma unroll
    for (int o = 16; o > 0; o >>= 1) s += __shfl_xor_sync(0xffffffffu, s, o);
    if ((k & 31) == 0) wsum[k >> 5] = s;
    __syncthreads();
    if (k < 32) {
        float t = wsum[k];
#pragma unroll
        for (int o = 16; o > 0; o >>= 1) t += __shfl_xor_sync(0xffffffffu, t, o);
        if (k == 0) Ssh = t;
    }
    __syncthreads();
    float S = Ssh;

    float csa = (c + 1e-9f) / (1.0f + (float)(1e-9 * 1024.0) / S);
    oCs[k] = csa;
    g_csa[k] = csa;
    if (k == 0) oLoss[0] = 0.25f * g_loss[0] / (float)NV;
}

// NOTE: oEn/oMa are offset by +1 float in d_out (loss scalar) -> NOT 16B aligned.
// Vector loads only from aligned sources; scalar stores to outputs.
__global__ void vq_fin2(const float* __restrict__ mavg,
                        float* __restrict__ oEn, float* __restrict__ oMa) {
    const float G = 0.99f;
    const float OMG = (float)(1.0 - 0.99);
    int i4 = blockIdx.x * blockDim.x + threadIdx.x;  // float4 index over K*D/4
    float4 mv = ((const float4*)mavg)[i4];
    float4 sv = ((const float4*)g_sums)[i4];
    float csa = g_csa[i4 >> 4];                      // 16 float4 per code row
    int b = i4 * 4;
    float m0 = G * mv.x + OMG * sv.x;
    float m1 = G * mv.y + OMG * sv.y;
    float m2 = G * mv.z + OMG * sv.z;
    float m3 = G * mv.w + OMG * sv.w;
    oMa[b + 0] = m0;  oEn[b + 0] = m0 / csa;
    oMa[b + 1] = m1;  oEn[b + 1] = m1 / csa;
    oMa[b + 2] = m2;  oEn[b + 2] = m2 / csa;
    oMa[b + 3] = m3;  oEn[b + 3] = m3 / csa;
}

// ---------------- launch ----------------
extern "C" void kernel_launch(void* const* d_in, const int* in_sizes, int n_in,
                              void* d_out, int out_size) {
    const float* X  = (const float*)d_in[0];
    const float* E  = (const float*)d_in[1];
    const float* cs = (const float*)d_in[2];
    const float* ma = (const float*)d_in[3];

    float* o = (float*)d_out;
    // output layout: Z[N*D], loss[1], argmins[N], min_dist[N], E_new[K*D], cs[K], ma[K*D]
    float* oZ    = o;
    float* oLoss = o + (size_t)NV * DC;
    float* oArg  = oLoss + 1;
    float* oMin  = oArg + NV;
    float* oEn   = oMin + NV;
    float* oCs   = oEn + (size_t)KC * DC;
    float* oMa   = oCs + KC;

    int smem = SMEM_FLOATS * 4;
    cudaFuncSetAttribute(vq_main, cudaFuncAttributeMaxDynamicSharedMemorySize, smem);

    vq_zero<<<(KC * DC / 4 + KC + 1 + 255) / 256, 256>>>();
    vq_esq<<<(KC + 255) / 256, 256>>>(E);
    vq_main<<<NV / TM, 256, smem>>>(X, E, oZ, oArg, oMin);
    vq_fin1<<<1, KC>>>(cs, oCs, oLoss);
    vq_fin2<<<KC * DC / 4 / 256, 256>>>(ma, oEn, oMa);
}

// round 7
// speedup vs baseline: 1.9353x; 1.1242x over previous
#include <cuda_runtime.h>
#include <cuda_bf16.h>
#include <cstdint>

#define KC 1024
#define DC 64
#define NV 131072
#define TM 128      // rows per CTA
#define NT 128      // threads (4 warps x 32 rows)

// ---------------- scratch ----------------
__device__ __align__(16) float g_esq[KC];
__device__ __align__(16) float g_counts[KC];
__device__ __align__(16) float g_sums[KC * DC];
__device__ float g_loss[1];
__device__ __align__(16) float g_csa[KC];
__device__ __align__(16) __nv_bfloat16 g_Ehi[KC * DC];
__device__ __align__(16) __nv_bfloat16 g_Elo[KC * DC];

// ---------------- mma helper (arch-neutral PTX, HMMA on sm_103) ----------------
__device__ __forceinline__ void mma16816(float& d0, float& d1, float& d2, float& d3,
                                         uint32_t a0, uint32_t a1, uint32_t a2, uint32_t a3,
                                         uint32_t b0, uint32_t b1) {
    asm volatile("mma.sync.aligned.m16n8k16.row.col.f32.bf16.bf16.f32 "
                 "{%0,%1,%2,%3}, {%4,%5,%6,%7}, {%8,%9}, {%0,%1,%2,%3};"
                 : "+f"(d0), "+f"(d1), "+f"(d2), "+f"(d3)
                 : "r"(a0), "r"(a1), "r"(a2), "r"(a3), "r"(b0), "r"(b1));
}

// ---------------- prep kernels ----------------
__global__ void vq_zero() {
    int i = blockIdx.x * blockDim.x + threadIdx.x;
    if (i < KC * DC / 4) {
        ((float4*)g_sums)[i] = make_float4(0.f, 0.f, 0.f, 0.f);
    } else if (i < KC * DC / 4 + KC) {
        g_counts[i - KC * DC / 4] = 0.f;
    } else if (i == KC * DC / 4 + KC) {
        g_loss[0] = 0.f;
    }
}

__global__ void vq_esq(const float* __restrict__ E) {
    int k = blockIdx.x * blockDim.x + threadIdx.x;
    if (k < KC) {
        const float4* r = (const float4*)(E + (size_t)k * DC);
        float s = 0.f;
#pragma unroll
        for (int q = 0; q < DC / 4; q++) {
            float4 v = r[q];
            s = fmaf(v.x, v.x, s); s = fmaf(v.y, v.y, s);
            s = fmaf(v.z, v.z, s); s = fmaf(v.w, v.w, s);
        }
        g_esq[k] = s;
    }
}

// split E into bf16 hi/lo
__global__ void vq_esplit(const float* __restrict__ E) {
    int i4 = blockIdx.x * blockDim.x + threadIdx.x;   // < KC*DC/4
    float4 v = ((const float4*)E)[i4];
    __nv_bfloat16 h0 = __float2bfloat16(v.x), h1 = __float2bfloat16(v.y);
    __nv_bfloat16 h2 = __float2bfloat16(v.z), h3 = __float2bfloat16(v.w);
    float l0 = v.x - __bfloat162float(h0), l1 = v.y - __bfloat162float(h1);
    float l2 = v.z - __bfloat162float(h2), l3 = v.w - __bfloat162float(h3);
    __nv_bfloat162* H = (__nv_bfloat162*)g_Ehi;
    __nv_bfloat162* L = (__nv_bfloat162*)g_Elo;
    H[i4 * 2] = __halves2bfloat162(h0, h1);
    H[i4 * 2 + 1] = __halves2bfloat162(h2, h3);
    L[i4 * 2] = __halves2bfloat162(__float2bfloat16(l0), __float2bfloat16(l1));
    L[i4 * 2 + 1] = __halves2bfloat162(__float2bfloat16(l2), __float2bfloat16(l3));
}

// ---------------- smem layout (bytes) ----------------
#define PITCH 72                              // bf16 per row (144B, conflict-free frags)
#define SM_XHI 0
#define SM_XLO (TM * PITCH * 2)               // 18432
#define SM_EB  (2 * TM * PITCH * 2)           // 36864
#define EBUF_SZ (64 * PITCH * 2)              // 9216 per split
#define SM_ESQ (SM_EB + 4 * EBUF_SZ)          // 73728
#define SM_RED (SM_ESQ + KC * 4)              // 77824
#define SM_TOTB (SM_RED + TM * 12)            // 79360

// ---------------- main kernel ----------------
extern "C" __global__ void __launch_bounds__(NT, 2)
vq_main_mma(const float* __restrict__ X, const float* __restrict__ E,
            float* __restrict__ oZ, float* __restrict__ oArg, float* __restrict__ oMin) {
    extern __shared__ char sm[];
    __nv_bfloat16* Xhi = (__nv_bfloat16*)(sm + SM_XHI);
    __nv_bfloat16* Xlo = (__nv_bfloat16*)(sm + SM_XLO);
    float* esq_s = (float*)(sm + SM_ESQ);
    float* rbest = (float*)(sm + SM_RED);
    float* rsec = rbest + TM;
    int* ridx = (int*)(rsec + TM);

    const int tid = threadIdx.x;
    const int wid = tid >> 5, lane = tid & 31;
    const int g = lane >> 2, c4 = lane & 3;
    const int rowb = wid * 32;

    for (int i = tid; i < KC; i += NT) esq_s[i] = g_esq[i];

    // X tile: load fp32, split to bf16 hi/lo in smem
    const float4* Xg4 = (const float4*)(X + (size_t)blockIdx.x * TM * DC);
#pragma unroll
    for (int j = 0; j < 16; j++) {
        int i4 = tid + NT * j;
        float4 v = Xg4[i4];
        int row = i4 >> 4, col = (i4 & 15) * 4;
        __nv_bfloat16 h0 = __float2bfloat16(v.x), h1 = __float2bfloat16(v.y);
        __nv_bfloat16 h2 = __float2bfloat16(v.z), h3 = __float2bfloat16(v.w);
        float l0 = v.x - __bfloat162float(h0), l1 = v.y - __bfloat162float(h1);
        float l2 = v.z - __bfloat162float(h2), l3 = v.w - __bfloat162float(h3);
        int off = row * PITCH + col;
        *(__nv_bfloat162*)(Xhi + off) = __halves2bfloat162(h0, h1);
        *(__nv_bfloat162*)(Xhi + off + 2) = __halves2bfloat162(h2, h3);
        *(__nv_bfloat162*)(Xlo + off) =
            __halves2bfloat162(__float2bfloat16(l0), __float2bfloat16(l1));
        *(__nv_bfloat162*)(Xlo + off + 2) =
            __halves2bfloat162(__float2bfloat16(l2), __float2bfloat16(l3));
    }
    __syncthreads();

    // A fragments held in registers for the whole kernel
    uint32_t ah[4][2][4], al[4][2][4];
#pragma unroll
    for (int k = 0; k < 4; k++)
#pragma unroll
        for (int mt = 0; mt < 2; mt++) {
            int r0 = rowb + mt * 16 + g;
            int cb = k * 16 + c4 * 2;
            ah[k][mt][0] = *(const uint32_t*)(Xhi + r0 * PITCH + cb);
            ah[k][mt][1] = *(const uint32_t*)(Xhi + (r0 + 8) * PITCH + cb);
            ah[k][mt][2] = *(const uint32_t*)(Xhi + r0 * PITCH + cb + 8);
            ah[k][mt][3] = *(const uint32_t*)(Xhi + (r0 + 8) * PITCH + cb + 8);
            al[k][mt][0] = *(const uint32_t*)(Xlo + r0 * PITCH + cb);
            al[k][mt][1] = *(const uint32_t*)(Xlo + (r0 + 8) * PITCH + cb);
            al[k][mt][2] = *(const uint32_t*)(Xlo + r0 * PITCH + cb + 8);
            al[k][mt][3] = *(const uint32_t*)(Xlo + (r0 + 8) * PITCH + cb + 8);
        }

    // E chunk copy (64 codes, hi+lo) into buffer b
#define COPY_E(ch, b) do {                                                        \
        const uint4* shh = (const uint4*)(g_Ehi + (ch) * 64 * DC);                \
        const uint4* sll = (const uint4*)(g_Elo + (ch) * 64 * DC);                \
        char* dst = sm + SM_EB + (b) * 2 * EBUF_SZ;                               \
        _Pragma("unroll")                                                          \
        for (int j = 0; j < 4; j++) {                                             \
            int q = tid + NT * j;                                                 \
            int code = q >> 3, cc = q & 7;                                        \
            *(uint4*)(dst + code * (PITCH * 2) + cc * 16) = shh[q];               \
            *(uint4*)(dst + EBUF_SZ + code * (PITCH * 2) + cc * 16) = sll[q];     \
        }                                                                          \
    } while (0)

    COPY_E(0, 0);

    float best[4], sec[4];
    int idx[4];
#pragma unroll
    for (int s = 0; s < 4; s++) { best[s] = 3.4e38f; sec[s] = 3.4e38f; idx[s] = 0; }
    __syncthreads();

    for (int ch = 0; ch < 16; ch++) {
        if (ch < 15) COPY_E(ch + 1, (ch + 1) & 1);
        const char* ebh = sm + SM_EB + (ch & 1) * 2 * EBUF_SZ;
        const char* ebl = ebh + EBUF_SZ;

        float acc[2][8][4];
#pragma unroll
        for (int mt = 0; mt < 2; mt++)
#pragma unroll
            for (int nt = 0; nt < 8; nt++)
#pragma unroll
                for (int r = 0; r < 4; r++) acc[mt][nt][r] = 0.f;

#pragma unroll
        for (int np = 0; np < 4; np++) {
            uint32_t bh[2][4][2], bl[2][4][2];
#pragma unroll
            for (int t = 0; t < 2; t++) {
                int nt = 2 * np + t;
                int coff = (nt * 8 + g) * (PITCH * 2) + c4 * 4;
#pragma unroll
                for (int k = 0; k < 4; k++) {
                    bh[t][k][0] = *(const uint32_t*)(ebh + coff + k * 32);
                    bh[t][k][1] = *(const uint32_t*)(ebh + coff + k * 32 + 16);
                    bl[t][k][0] = *(const uint32_t*)(ebl + coff + k * 32);
                    bl[t][k][1] = *(const uint32_t*)(ebl + coff + k * 32 + 16);
                }
            }
#pragma unroll
            for (int k = 0; k < 4; k++)
#pragma unroll
                for (int t = 0; t < 2; t++)
#pragma unroll
                    for (int mt = 0; mt < 2; mt++) {
                        float* a = acc[mt][2 * np + t];
                        mma16816(a[0], a[1], a[2], a[3],
                                 ah[k][mt][0], ah[k][mt][1], ah[k][mt][2], ah[k][mt][3],
                                 bh[t][k][0], bh[t][k][1]);
                        mma16816(a[0], a[1], a[2], a[3],
                                 ah[k][mt][0], ah[k][mt][1], ah[k][mt][2], ah[k][mt][3],
                                 bl[t][k][0], bl[t][k][1]);
                        mma16816(a[0], a[1], a[2], a[3],
                                 al[k][mt][0], al[k][mt][1], al[k][mt][2], al[k][mt][3],
                                 bh[t][k][0], bh[t][k][1]);
                    }
        }

        // chunk epilogue: dist-without-xsq = esq - 2*dot
#pragma unroll
        for (int nt = 0; nt < 8; nt++) {
            int c0 = ch * 64 + nt * 8 + c4 * 2;
            float e0 = esq_s[c0], e1 = esq_s[c0 + 1];
#pragma unroll
            for (int mt = 0; mt < 2; mt++) {
                float d0 = fmaf(-2.f, acc[mt][nt][0], e0);
                float d1 = fmaf(-2.f, acc[mt][nt][1], e1);
                float d2 = fmaf(-2.f, acc[mt][nt][2], e0);
                float d3 = fmaf(-2.f, acc[mt][nt][3], e1);
                int s0 = 2 * mt, s1 = 2 * mt + 1;
                if (d0 < best[s0]) { sec[s0] = best[s0]; best[s0] = d0; idx[s0] = c0; }
                else if (d0 < sec[s0]) sec[s0] = d0;
                if (d1 < best[s0]) { sec[s0] = best[s0]; best[s0] = d1; idx[s0] = c0 + 1; }
                else if (d1 < sec[s0]) sec[s0] = d1;
                if (d2 < best[s1]) { sec[s1] = best[s1]; best[s1] = d2; idx[s1] = c0; }
                else if (d2 < sec[s1]) sec[s1] = d2;
                if (d3 < best[s1]) { sec[s1] = best[s1]; best[s1] = d3; idx[s1] = c0 + 1; }
                else if (d3 < sec[s1]) sec[s1] = d3;
            }
        }
        __syncthreads();
    }

    // merge across the 4 lanes of each quad (same g, c4 = 0..3)
#pragma unroll
    for (int s = 0; s < 4; s++) {
#pragma unroll
        for (int o = 1; o < 4; o <<= 1) {
            float ob = __shfl_xor_sync(0xffffffffu, best[s], o);
            float os = __shfl_xor_sync(0xffffffffu, sec[s], o);
            int oi = __shfl_xor_sync(0xffffffffu, idx[s], o);
            if (ob < best[s] || (ob == best[s] && oi < idx[s])) {
                sec[s] = fminf(fminf(sec[s], os), best[s]);
                best[s] = ob; idx[s] = oi;
            } else {
                sec[s] = fminf(fminf(sec[s], os), ob);
            }
        }
        int row = rowb + (s >> 1) * 16 + ((s & 1) << 3) + g;
        if (c4 == 0) { rbest[row] = best[s]; rsec[row] = sec[s]; ridx[row] = idx[s]; }
    }
    __syncthreads();

    // per-row state (thread = row)
    float bd = rbest[tid], sd = rsec[tid];
    int bi = ridx[tid];

    // deterministic exact-fp32 rescue for ambiguous rows
    bool flagged = (sd - bd < 0.02f);
    unsigned fl = __ballot_sync(0xffffffffu, flagged);
    while (fl) {
        int fr = __ffs(fl) - 1; fl &= fl - 1;
        int rr = wid * 32 + fr;
        const float4* xrr = (const float4*)(X + ((size_t)blockIdx.x * TM + rr) * DC);
        float xv[64];
#pragma unroll
        for (int q = 0; q < 16; q++) {
            float4 v = xrr[q];
            xv[4 * q] = v.x; xv[4 * q + 1] = v.y; xv[4 * q + 2] = v.z; xv[4 * q + 3] = v.w;
        }
        float bb = 3.4e38f; int bj = 0;
        for (int c = lane; c < KC; c += 32) {
            const float4* er = (const float4*)(E + (size_t)c * DC);
            float dot = 0.f;
#pragma unroll
            for (int q = 0; q < 16; q++) {
                float4 e4 = er[q];
                dot = fmaf(xv[4 * q], e4.x, dot);
                dot = fmaf(xv[4 * q + 1], e4.y, dot);
                dot = fmaf(xv[4 * q + 2], e4.z, dot);
                dot = fmaf(xv[4 * q + 3], e4.w, dot);
            }
            float pd = fmaf(-2.f, dot, esq_s[c]);
            if (pd < bb) { bb = pd; bj = c; }
        }
#pragma unroll
        for (int o = 16; o > 0; o >>= 1) {
            float ov = __shfl_xor_sync(0xffffffffu, bb, o);
            int oi = __shfl_xor_sync(0xffffffffu, bj, o);
            if (ov < bb || (ov == bb && oi < bj)) { bb = ov; bj = oi; }
        }
        if (lane == fr) { bd = bb; bi = bj; }
    }

    // writeout (thread = row), exact X from gmem
    {
        size_t gr = (size_t)blockIdx.x * TM + tid;
        const float4* xr = (const float4*)(X + gr * DC);
        const float4* er = (const float4*)(E + (size_t)bi * DC);
        float4* Zr = (float4*)(oZ + gr * DC);
        float xsq = 0.f, lsum = 0.f;
        atomicAdd(&g_counts[bi], 1.0f);
        float* srow = &g_sums[bi * DC];
#pragma unroll
        for (int q = 0; q < 16; q++) {
            float4 xv4 = xr[q];
            float4 e4 = er[q];
            float d0 = e4.x - xv4.x, d1 = e4.y - xv4.y;
            float d2 = e4.z - xv4.z, d3 = e4.w - xv4.w;
            float4 z;
            z.x = xv4.x + d0; z.y = xv4.y + d1; z.z = xv4.z + d2; z.w = xv4.w + d3;
            Zr[q] = z;
            lsum = fmaf(d0, d0, lsum); lsum = fmaf(d1, d1, lsum);
            lsum = fmaf(d2, d2, lsum); lsum = fmaf(d3, d3, lsum);
            xsq = fmaf(xv4.x, xv4.x, xsq); xsq = fmaf(xv4.y, xv4.y, xsq);
            xsq = fmaf(xv4.z, xv4.z, xsq); xsq = fmaf(xv4.w, xv4.w, xsq);
            atomicAdd(srow + 4 * q + 0, xv4.x);
            atomicAdd(srow + 4 * q + 1, xv4.y);
            atomicAdd(srow + 4 * q + 2, xv4.z);
            atomicAdd(srow + 4 * q + 3, xv4.w);
        }
        oMin[gr] = xsq + bd;
        oArg[gr] = (float)bi;
#pragma unroll
        for (int o = 16; o > 0; o >>= 1) lsum += __shfl_xor_sync(0xffffffffu, lsum, o);
        if (lane == 0) atomicAdd(g_loss, lsum);
    }
}

// ---------------- finalize ----------------
__global__ void vq_fin1(const float* __restrict__ cs_in,
                        float* __restrict__ oCs, float* __restrict__ oLoss) {
    __shared__ float wsum[32];
    __shared__ float Ssh;
    int k = threadIdx.x;
    const float G = 0.99f;
    const float OMG = (float)(1.0 - 0.99);
    float c = G * cs_in[k] + OMG * g_counts[k];

    float s = c;
#pragma unroll
    for (int o = 16; o > 0; o >>= 1) s += __shfl_xor_sync(0xffffffffu, s, o);
    if ((k & 31) == 0) wsum[k >> 5] = s;
    __syncthreads();
    if (k < 32) {
        float t = wsum[k];
#pragma unroll
        for (int o = 16; o > 0; o >>= 1) t += __shfl_xor_sync(0xffffffffu, t, o);
        if (k == 0) Ssh = t;
    }
    __syncthreads();
    float S = Ssh;

    float csa = (c + 1e-9f) / (1.0f + (float)(1e-9 * 1024.0) / S);
    oCs[k] = csa;
    g_csa[k] = csa;
    if (k == 0) oLoss[0] = 0.25f * g_loss[0] / (float)NV;
}

// oEn/oMa offset by +1 float in d_out -> scalar stores only
__global__ void vq_fin2(const float* __restrict__ mavg,
                        float* __restrict__ oEn, float* __restrict__ oMa) {
    const float G = 0.99f;
    const float OMG = (float)(1.0 - 0.99);
    int i4 = blockIdx.x * blockDim.x + threadIdx.x;
    float4 mv = ((const float4*)mavg)[i4];
    float4 sv = ((const float4*)g_sums)[i4];
    float csa = g_csa[i4 >> 4];
    int b = i4 * 4;
    float m0 = G * mv.x + OMG * sv.x;
    float m1 = G * mv.y + OMG * sv.y;
    float m2 = G * mv.z + OMG * sv.z;
    float m3 = G * mv.w + OMG * sv.w;
    oMa[b + 0] = m0;  oEn[b + 0] = m0 / csa;
    oMa[b + 1] = m1;  oEn[b + 1] = m1 / csa;
    oMa[b + 2] = m2;  oEn[b + 2] = m2 / csa;
    oMa[b + 3] = m3;  oEn[b + 3] = m3 / csa;
}

// ---------------- launch ----------------
extern "C" void kernel_launch(void* const* d_in, const int* in_sizes, int n_in,
                              void* d_out, int out_size) {
    const float* X  = (const float*)d_in[0];
    const float* E  = (const float*)d_in[1];
    const float* cs = (const float*)d_in[2];
    const float* ma = (const float*)d_in[3];

    float* o = (float*)d_out;
    float* oZ    = o;
    float* oLoss = o + (size_t)NV * DC;
    float* oArg  = oLoss + 1;
    float* oMin  = oArg + NV;
    float* oEn   = oMin + NV;
    float* oCs   = oEn + (size_t)KC * DC;
    float* oMa   = oCs + KC;

    cudaFuncSetAttribute(vq_main_mma, cudaFuncAttributeMaxDynamicSharedMemorySize, SM_TOTB);

    vq_zero<<<(KC * DC / 4 + KC + 1 + 255) / 256, 256>>>();
    vq_esq<<<(KC + 255) / 256, 256>>>(E);
    vq_esplit<<<KC * DC / 4 / 256, 256>>>(E);
    vq_main_mma<<<NV / TM, NT, SM_TOTB>>>(X, E, oZ, oArg, oMin);
    vq_fin1<<<1, KC>>>(cs, oCs, oLoss);
    vq_fin2<<<KC * DC / 4 / 256, 256>>>(ma, oEn, oMa);
}

// round 9
// speedup vs baseline: 1.9434x; 1.0042x over previous
#include <cuda_runtime.h>
#include <cuda_bf16.h>
#include <cstdint>

#define KC 1024
#define DC 64
#define NV 131072
#define TM 128      // rows per CTA
#define NT 128      // threads (4 warps x 32 rows)

// ---------------- scratch ----------------
__device__ __align__(16) float g_esq[KC];
__device__ __align__(16) float g_counts[KC];
__device__ __align__(16) float g_sums[KC * DC];
__device__ float g_loss[1];
__device__ __align__(16) float g_csa[KC];
__device__ __align__(16) __nv_bfloat16 g_Ehi[KC * DC];
__device__ __align__(16) __nv_bfloat16 g_Elo[KC * DC];

// ---------------- mma helper (arch-neutral PTX, HMMA on sm_103) ----------------
__device__ __forceinline__ void mma16816(float& d0, float& d1, float& d2, float& d3,
                                         uint32_t a0, uint32_t a1, uint32_t a2, uint32_t a3,
                                         uint32_t b0, uint32_t b1) {
    asm volatile("mma.sync.aligned.m16n8k16.row.col.f32.bf16.bf16.f32 "
                 "{%0,%1,%2,%3}, {%4,%5,%6,%7}, {%8,%9}, {%0,%1,%2,%3};"
                 : "+f"(d0), "+f"(d1), "+f"(d2), "+f"(d3)
                 : "r"(a0), "r"(a1), "r"(a2), "r"(a3), "r"(b0), "r"(b1));
}

// ---------------- prep kernels ----------------
__global__ void vq_zero() {
    int i = blockIdx.x * blockDim.x + threadIdx.x;
    if (i < KC * DC / 4) {
        ((float4*)g_sums)[i] = make_float4(0.f, 0.f, 0.f, 0.f);
    } else if (i < KC * DC / 4 + KC) {
        g_counts[i - KC * DC / 4] = 0.f;
    } else if (i == KC * DC / 4 + KC) {
        g_loss[0] = 0.f;
    }
}

__global__ void vq_esq(const float* __restrict__ E) {
    int k = blockIdx.x * blockDim.x + threadIdx.x;
    if (k < KC) {
        const float4* r = (const float4*)(E + (size_t)k * DC);
        float s = 0.f;
#pragma unroll
        for (int q = 0; q < DC / 4; q++) {
            float4 v = r[q];
            s = fmaf(v.x, v.x, s); s = fmaf(v.y, v.y, s);
            s = fmaf(v.z, v.z, s); s = fmaf(v.w, v.w, s);
        }
        g_esq[k] = s;
    }
}

// split E into bf16 hi/lo
__global__ void vq_esplit(const float* __restrict__ E) {
    int i4 = blockIdx.x * blockDim.x + threadIdx.x;   // < KC*DC/4
    float4 v = ((const float4*)E)[i4];
    __nv_bfloat16 h0 = __float2bfloat16(v.x), h1 = __float2bfloat16(v.y);
    __nv_bfloat16 h2 = __float2bfloat16(v.z), h3 = __float2bfloat16(v.w);
    float l0 = v.x - __bfloat162float(h0), l1 = v.y - __bfloat162float(h1);
    float l2 = v.z - __bfloat162float(h2), l3 = v.w - __bfloat162float(h3);
    __nv_bfloat162* H = (__nv_bfloat162*)g_Ehi;
    __nv_bfloat162* L = (__nv_bfloat162*)g_Elo;
    H[i4 * 2] = __halves2bfloat162(h0, h1);
    H[i4 * 2 + 1] = __halves2bfloat162(h2, h3);
    L[i4 * 2] = __halves2bfloat162(__float2bfloat16(l0), __float2bfloat16(l1));
    L[i4 * 2 + 1] = __halves2bfloat162(__float2bfloat16(l2), __float2bfloat16(l3));
}

// ---------------- smem layout (bytes) ----------------
#define PITCH 72                              // bf16 per row (144B, conflict-free frags)
#define SM_XHI 0
#define SM_XLO (TM * PITCH * 2)               // 18432
#define SM_EB  (2 * TM * PITCH * 2)           // 36864
#define EBUF_SZ (64 * PITCH * 2)              // 9216 per split
#define SM_ESQ (SM_EB + 4 * EBUF_SZ)          // 73728
#define SM_RED (SM_ESQ + KC * 4)              // 77824
#define SM_TOTB (SM_RED + TM * 12)            // 79360

// ---------------- main kernel ----------------
extern "C" __global__ void __launch_bounds__(NT, 2)
vq_main_mma(const float* __restrict__ X, const float* __restrict__ E,
            float* __restrict__ oZ, float* __restrict__ oArg, float* __restrict__ oMin) {
    extern __shared__ char sm[];
    __nv_bfloat16* Xhi = (__nv_bfloat16*)(sm + SM_XHI);
    __nv_bfloat16* Xlo = (__nv_bfloat16*)(sm + SM_XLO);
    float* esq_s = (float*)(sm + SM_ESQ);
    float* rbest = (float*)(sm + SM_RED);
    float* rsec = rbest + TM;
    int* ridx = (int*)(rsec + TM);

    const int tid = threadIdx.x;
    const int wid = tid >> 5, lane = tid & 31;
    const int g = lane >> 2, c4 = lane & 3;
    const int rowb = wid * 32;

    for (int i = tid; i < KC; i += NT) esq_s[i] = g_esq[i];

    // X tile: load fp32, split to bf16 hi/lo in smem
    const float4* Xg4 = (const float4*)(X + (size_t)blockIdx.x * TM * DC);
#pragma unroll
    for (int j = 0; j < 16; j++) {
        int i4 = tid + NT * j;
        float4 v = Xg4[i4];
        int row = i4 >> 4, col = (i4 & 15) * 4;
        __nv_bfloat16 h0 = __float2bfloat16(v.x), h1 = __float2bfloat16(v.y);
        __nv_bfloat16 h2 = __float2bfloat16(v.z), h3 = __float2bfloat16(v.w);
        float l0 = v.x - __bfloat162float(h0), l1 = v.y - __bfloat162float(h1);
        float l2 = v.z - __bfloat162float(h2), l3 = v.w - __bfloat162float(h3);
        int off = row * PITCH + col;
        *(__nv_bfloat162*)(Xhi + off) = __halves2bfloat162(h0, h1);
        *(__nv_bfloat162*)(Xhi + off + 2) = __halves2bfloat162(h2, h3);
        *(__nv_bfloat162*)(Xlo + off) =
            __halves2bfloat162(__float2bfloat16(l0), __float2bfloat16(l1));
        *(__nv_bfloat162*)(Xlo + off + 2) =
            __halves2bfloat162(__float2bfloat16(l2), __float2bfloat16(l3));
    }
    __syncthreads();

    // A fragments held in registers for the whole kernel
    uint32_t ah[4][2][4], al[4][2][4];
#pragma unroll
    for (int k = 0; k < 4; k++)
#pragma unroll
        for (int mt = 0; mt < 2; mt++) {
            int r0 = rowb + mt * 16 + g;
            int cb = k * 16 + c4 * 2;
            ah[k][mt][0] = *(const uint32_t*)(Xhi + r0 * PITCH + cb);
            ah[k][mt][1] = *(const uint32_t*)(Xhi + (r0 + 8) * PITCH + cb);
            ah[k][mt][2] = *(const uint32_t*)(Xhi + r0 * PITCH + cb + 8);
            ah[k][mt][3] = *(const uint32_t*)(Xhi + (r0 + 8) * PITCH + cb + 8);
            al[k][mt][0] = *(const uint32_t*)(Xlo + r0 * PITCH + cb);
            al[k][mt][1] = *(const uint32_t*)(Xlo + (r0 + 8) * PITCH + cb);
            al[k][mt][2] = *(const uint32_t*)(Xlo + r0 * PITCH + cb + 8);
            al[k][mt][3] = *(const uint32_t*)(Xlo + (r0 + 8) * PITCH + cb + 8);
        }

    // E chunk copy (64 codes, hi+lo) into buffer b
#define COPY_E(ch, b) do {                                                        \
        const uint4* shh = (const uint4*)(g_Ehi + (ch) * 64 * DC);                \
        const uint4* sll = (const uint4*)(g_Elo + (ch) * 64 * DC);                \
        char* dst = sm + SM_EB + (b) * 2 * EBUF_SZ;                               \
        _Pragma("unroll")                                                          \
        for (int j = 0; j < 4; j++) {                                             \
            int q = tid + NT * j;                                                 \
            int code = q >> 3, cc = q & 7;                                        \
            *(uint4*)(dst + code * (PITCH * 2) + cc * 16) = shh[q];               \
            *(uint4*)(dst + EBUF_SZ + code * (PITCH * 2) + cc * 16) = sll[q];     \
        }                                                                          \
    } while (0)

    COPY_E(0, 0);

    float best[4], sec[4];
    int idx[4];
#pragma unroll
    for (int s = 0; s < 4; s++) { best[s] = 3.4e38f; sec[s] = 3.4e38f; idx[s] = 0; }
    __syncthreads();

    for (int ch = 0; ch < 16; ch++) {
        if (ch < 15) COPY_E(ch + 1, (ch + 1) & 1);
        const char* ebh = sm + SM_EB + (ch & 1) * 2 * EBUF_SZ;
        const char* ebl = ebh + EBUF_SZ;

        float acc[2][8][4];
#pragma unroll
        for (int mt = 0; mt < 2; mt++)
#pragma unroll
            for (int nt = 0; nt < 8; nt++)
#pragma unroll
                for (int r = 0; r < 4; r++) acc[mt][nt][r] = 0.f;

#pragma unroll
        for (int np = 0; np < 4; np++) {
            uint32_t bh[2][4][2], bl[2][4][2];
#pragma unroll
            for (int t = 0; t < 2; t++) {
                int nt = 2 * np + t;
                int coff = (nt * 8 + g) * (PITCH * 2) + c4 * 4;
#pragma unroll
                for (int k = 0; k < 4; k++) {
                    bh[t][k][0] = *(const uint32_t*)(ebh + coff + k * 32);
                    bh[t][k][1] = *(const uint32_t*)(ebh + coff + k * 32 + 16);
                    bl[t][k][0] = *(const uint32_t*)(ebl + coff + k * 32);
                    bl[t][k][1] = *(const uint32_t*)(ebl + coff + k * 32 + 16);
                }
            }
            // product-major ordering: same-acc MMAs are 4 apart (dep distance >= lat)
#pragma unroll
            for (int k = 0; k < 4; k++) {
#pragma unroll
                for (int t = 0; t < 2; t++)
#pragma unroll
                    for (int mt = 0; mt < 2; mt++) {
                        float* a = acc[mt][2 * np + t];
                        mma16816(a[0], a[1], a[2], a[3],
                                 ah[k][mt][0], ah[k][mt][1], ah[k][mt][2], ah[k][mt][3],
                                 bh[t][k][0], bh[t][k][1]);
                    }
#pragma unroll
                for (int t = 0; t < 2; t++)
#pragma unroll
                    for (int mt = 0; mt < 2; mt++) {
                        float* a = acc[mt][2 * np + t];
                        mma16816(a[0], a[1], a[2], a[3],
                                 ah[k][mt][0], ah[k][mt][1], ah[k][mt][2], ah[k][mt][3],
                                 bl[t][k][0], bl[t][k][1]);
                    }
#pragma unroll
                for (int t = 0; t < 2; t++)
#pragma unroll
                    for (int mt = 0; mt < 2; mt++) {
                        float* a = acc[mt][2 * np + t];
                        mma16816(a[0], a[1], a[2], a[3],
                                 al[k][mt][0], al[k][mt][1], al[k][mt][2], al[k][mt][3],
                                 bh[t][k][0], bh[t][k][1]);
                    }
            }
        }

        // chunk epilogue: dist-without-xsq = esq - 2*dot
#pragma unroll
        for (int nt = 0; nt < 8; nt++) {
            int c0 = ch * 64 + nt * 8 + c4 * 2;
            float e0 = esq_s[c0], e1 = esq_s[c0 + 1];
#pragma unroll
            for (int mt = 0; mt < 2; mt++) {
                float d0 = fmaf(-2.f, acc[mt][nt][0], e0);
                float d1 = fmaf(-2.f, acc[mt][nt][1], e1);
                float d2 = fmaf(-2.f, acc[mt][nt][2], e0);
                float d3 = fmaf(-2.f, acc[mt][nt][3], e1);
                int s0 = 2 * mt, s1 = 2 * mt + 1;
                if (d0 < best[s0]) { sec[s0] = best[s0]; best[s0] = d0; idx[s0] = c0; }
                else if (d0 < sec[s0]) sec[s0] = d0;
                if (d1 < best[s0]) { sec[s0] = best[s0]; best[s0] = d1; idx[s0] = c0 + 1; }
                else if (d1 < sec[s0]) sec[s0] = d1;
                if (d2 < best[s1]) { sec[s1] = best[s1]; best[s1] = d2; idx[s1] = c0; }
                else if (d2 < sec[s1]) sec[s1] = d2;
                if (d3 < best[s1]) { sec[s1] = best[s1]; best[s1] = d3; idx[s1] = c0 + 1; }
                else if (d3 < sec[s1]) sec[s1] = d3;
            }
        }
        __syncthreads();
    }

    // merge across the 4 lanes of each quad (same g, c4 = 0..3)
#pragma unroll
    for (int s = 0; s < 4; s++) {
#pragma unroll
        for (int o = 1; o < 4; o <<= 1) {
            float ob = __shfl_xor_sync(0xffffffffu, best[s], o);
            float os = __shfl_xor_sync(0xffffffffu, sec[s], o);
            int oi = __shfl_xor_sync(0xffffffffu, idx[s], o);
            if (ob < best[s] || (ob == best[s] && oi < idx[s])) {
                sec[s] = fminf(fminf(sec[s], os), best[s]);
                best[s] = ob; idx[s] = oi;
            } else {
                sec[s] = fminf(fminf(sec[s], os), ob);
            }
        }
        int row = rowb + (s >> 1) * 16 + ((s & 1) << 3) + g;
        if (c4 == 0) { rbest[row] = best[s]; rsec[row] = sec[s]; ridx[row] = idx[s]; }
    }
    __syncthreads();

    // per-row state (thread = row)
    float bd = rbest[tid], sd = rsec[tid];
    int bi = ridx[tid];

    // deterministic exact-fp32 rescue for ambiguous rows
    bool flagged = (sd - bd < 0.02f);
    unsigned fl = __ballot_sync(0xffffffffu, flagged);
    while (fl) {
        int fr = __ffs(fl) - 1; fl &= fl - 1;
        int rr = wid * 32 + fr;
        const float4* xrr = (const float4*)(X + ((size_t)blockIdx.x * TM + rr) * DC);
        float xv[64];
#pragma unroll
        for (int q = 0; q < 16; q++) {
            float4 v = xrr[q];
            xv[4 * q] = v.x; xv[4 * q + 1] = v.y; xv[4 * q + 2] = v.z; xv[4 * q + 3] = v.w;
        }
        float bb = 3.4e38f; int bj = 0;
        for (int c = lane; c < KC; c += 32) {
            const float4* er = (const float4*)(E + (size_t)c * DC);
            float dot = 0.f;
#pragma unroll
            for (int q = 0; q < 16; q++) {
                float4 e4 = er[q];
                dot = fmaf(xv[4 * q], e4.x, dot);
                dot = fmaf(xv[4 * q + 1], e4.y, dot);
                dot = fmaf(xv[4 * q + 2], e4.z, dot);
                dot = fmaf(xv[4 * q + 3], e4.w, dot);
            }
            float pd = fmaf(-2.f, dot, esq_s[c]);
            if (pd < bb) { bb = pd; bj = c; }
        }
#pragma unroll
        for (int o = 16; o > 0; o >>= 1) {
            float ov = __shfl_xor_sync(0xffffffffu, bb, o);
            int oi = __shfl_xor_sync(0xffffffffu, bj, o);
            if (ov < bb || (ov == bb && oi < bj)) { bb = ov; bj = oi; }
        }
        if (lane == fr) { bd = bb; bi = bj; }
    }

    // writeout (thread = row), exact X from gmem
    {
        size_t gr = (size_t)blockIdx.x * TM + tid;
        const float4* xr = (const float4*)(X + gr * DC);
        const float4* er = (const float4*)(E + (size_t)bi * DC);
        float4* Zr = (float4*)(oZ + gr * DC);
        float xsq = 0.f, lsum = 0.f;
        atomicAdd(&g_counts[bi], 1.0f);
        float* srow = &g_sums[bi * DC];
#pragma unroll
        for (int q = 0; q < 16; q++) {
            float4 xv4 = xr[q];
            float4 e4 = er[q];
            float d0 = e4.x - xv4.x, d1 = e4.y - xv4.y;
            float d2 = e4.z - xv4.z, d3 = e4.w - xv4.w;
            float4 z;
            z.x = xv4.x + d0; z.y = xv4.y + d1; z.z = xv4.z + d2; z.w = xv4.w + d3;
            Zr[q] = z;
            lsum = fmaf(d0, d0, lsum); lsum = fmaf(d1, d1, lsum);
            lsum = fmaf(d2, d2, lsum); lsum = fmaf(d3, d3, lsum);
            xsq = fmaf(xv4.x, xv4.x, xsq); xsq = fmaf(xv4.y, xv4.y, xsq);
            xsq = fmaf(xv4.z, xv4.z, xsq); xsq = fmaf(xv4.w, xv4.w, xsq);
            atomicAdd(srow + 4 * q + 0, xv4.x);
            atomicAdd(srow + 4 * q + 1, xv4.y);
            atomicAdd(srow + 4 * q + 2, xv4.z);
            atomicAdd(srow + 4 * q + 3, xv4.w);
        }
        oMin[gr] = xsq + bd;
        oArg[gr] = (float)bi;
#pragma unroll
        for (int o = 16; o > 0; o >>= 1) lsum += __shfl_xor_sync(0xffffffffu, lsum, o);
        if (lane == 0) atomicAdd(g_loss, lsum);
    }
}

// ---------------- finalize ----------------
__global__ void vq_fin1(const float* __restrict__ cs_in,
                        float* __restrict__ oCs, float* __restrict__ oLoss) {
    __shared__ float wsum[32];
    __shared__ float Ssh;
    int k = threadIdx.x;
    const float G = 0.99f;
    const float OMG = (float)(1.0 - 0.99);
    float c = G * cs_in[k] + OMG * g_counts[k];

    float s = c;
#pragma unroll
    for (int o = 16; o > 0; o >>= 1) s += __shfl_xor_sync(0xffffffffu, s, o);
    if ((k & 31) == 0) wsum[k >> 5] = s;
    __syncthreads();
    if (k < 32) {
        float t = wsum[k];
#pragma unroll
        for (int o = 16; o > 0; o >>= 1) t += __shfl_xor_sync(0xffffffffu, t, o);
        if (k == 0) Ssh = t;
    }
    __syncthreads();
    float S = Ssh;

    float csa = (c + 1e-9f) / (1.0f + (float)(1e-9 * 1024.0) / S);
    oCs[k] = csa;
    g_csa[k] = csa;
    if (k == 0) oLoss[0] = 0.25f * g_loss[0] / (float)NV;
}

// oEn/oMa offset by +1 float in d_out -> scalar stores only
__global__ void vq_fin2(const float* __restrict__ mavg,
                        float* __restrict__ oEn, float* __restrict__ oMa) {
    const float G = 0.99f;
    const float OMG = (float)(1.0 - 0.99);
    int i4 = blockIdx.x * blockDim.x + threadIdx.x;
    float4 mv = ((const float4*)mavg)[i4];
    float4 sv = ((const float4*)g_sums)[i4];
    float csa = g_csa[i4 >> 4];
    int b = i4 * 4;
    float m0 = G * mv.x + OMG * sv.x;
    float m1 = G * mv.y + OMG * sv.y;
    float m2 = G * mv.z + OMG * sv.z;
    float m3 = G * mv.w + OMG * sv.w;
    oMa[b + 0] = m0;  oEn[b + 0] = m0 / csa;
    oMa[b + 1] = m1;  oEn[b + 1] = m1 / csa;
    oMa[b + 2] = m2;  oEn[b + 2] = m2 / csa;
    oMa[b + 3] = m3;  oEn[b + 3] = m3 / csa;
}

// ---------------- launch ----------------
extern "C" void kernel_launch(void* const* d_in, const int* in_sizes, int n_in,
                              void* d_out, int out_size) {
    const float* X  = (const float*)d_in[0];
    const float* E  = (const float*)d_in[1];
    const float* cs = (const float*)d_in[2];
    const float* ma = (const float*)d_in[3];

    float* o = (float*)d_out;
    float* oZ    = o;
    float* oLoss = o + (size_t)NV * DC;
    float* oArg  = oLoss + 1;
    float* oMin  = oArg + NV;
    float* oEn   = oMin + NV;
    float* oCs   = oEn + (size_t)KC * DC;
    float* oMa   = oCs + KC;

    cudaFuncSetAttribute(vq_main_mma, cudaFuncAttributeMaxDynamicSharedMemorySize, SM_TOTB);

    vq_zero<<<(KC * DC / 4 + KC + 1 + 255) / 256, 256>>>();
    vq_esq<<<(KC + 255) / 256, 256>>>(E);
    vq_esplit<<<KC * DC / 4 / 256, 256>>>(E);
    vq_main_mma<<<NV / TM, NT, SM_TOTB>>>(X, E, oZ, oArg, oMin);
    vq_fin1<<<1, KC>>>(cs, oCs, oLoss);
    vq_fin2<<<KC * DC / 4 / 256, 256>>>(ma, oEn, oMa);
}

// round 10
// speedup vs baseline: 2.1397x; 1.1010x over previous
#include <cuda_runtime.h>
#include <cuda_fp16.h>
#include <cstdint>

#define KC 1024
#define DC 64
#define NV 131072
#define TM 128      // rows per CTA
#define NT 256      // threads (8 warps x 16 rows)

// ---------------- scratch ----------------
__device__ __align__(16) float g_esq[KC];
__device__ __align__(16) float g_counts[KC];
__device__ __align__(16) float g_sums[KC * DC];
__device__ float g_loss[1];
__device__ __align__(16) float g_csa[KC];
__device__ __align__(16) __half g_Ehi[KC * DC];
__device__ __align__(16) __half g_Elo[KC * DC];

// ---------------- PTX helpers (arch-neutral) ----------------
__device__ __forceinline__ void mma16816(float* a,
                                         uint32_t a0, uint32_t a1, uint32_t a2, uint32_t a3,
                                         uint32_t b0, uint32_t b1) {
    asm volatile("mma.sync.aligned.m16n8k16.row.col.f32.f16.f16.f32 "
                 "{%0,%1,%2,%3}, {%4,%5,%6,%7}, {%8,%9}, {%0,%1,%2,%3};"
                 : "+f"(a[0]), "+f"(a[1]), "+f"(a[2]), "+f"(a[3])
                 : "r"(a0), "r"(a1), "r"(a2), "r"(a3), "r"(b0), "r"(b1));
}
__device__ __forceinline__ void ldsm4(uint32_t& r0, uint32_t& r1, uint32_t& r2, uint32_t& r3,
                                      uint32_t addr) {
    asm volatile("ldmatrix.sync.aligned.m8n8.x4.shared.b16 {%0,%1,%2,%3}, [%4];"
                 : "=r"(r0), "=r"(r1), "=r"(r2), "=r"(r3) : "r"(addr));
}
__device__ __forceinline__ uint32_t smem_u32(const void* p) {
    uint32_t a;
    asm("{ .reg .u64 t; cvta.to.shared.u64 t, %1; cvt.u32.u64 %0, t; }" : "=r"(a) : "l"(p));
    return a;
}

// ---------------- prep kernels ----------------
__global__ void vq_zero() {
    int i = blockIdx.x * blockDim.x + threadIdx.x;
    if (i < KC * DC / 4) {
        ((float4*)g_sums)[i] = make_float4(0.f, 0.f, 0.f, 0.f);
    } else if (i < KC * DC / 4 + KC) {
        g_counts[i - KC * DC / 4] = 0.f;
    } else if (i == KC * DC / 4 + KC) {
        g_loss[0] = 0.f;
    }
}

__global__ void vq_esq(const float* __restrict__ E) {
    int k = blockIdx.x * blockDim.x + threadIdx.x;
    if (k < KC) {
        const float4* r = (const float4*)(E + (size_t)k * DC);
        float s = 0.f;
#pragma unroll
        for (int q = 0; q < DC / 4; q++) {
            float4 v = r[q];
            s = fmaf(v.x, v.x, s); s = fmaf(v.y, v.y, s);
            s = fmaf(v.z, v.z, s); s = fmaf(v.w, v.w, s);
        }
        g_esq[k] = s;
    }
}

// split E into fp16 hi/lo
__global__ void vq_esplit(const float* __restrict__ E) {
    int i4 = blockIdx.x * blockDim.x + threadIdx.x;   // < KC*DC/4
    float4 v = ((const float4*)E)[i4];
    __half h0 = __float2half_rn(v.x), h1 = __float2half_rn(v.y);
    __half h2 = __float2half_rn(v.z), h3 = __float2half_rn(v.w);
    float l0 = v.x - __half2float(h0), l1 = v.y - __half2float(h1);
    float l2 = v.z - __half2float(h2), l3 = v.w - __half2float(h3);
    __half2* H = (__half2*)g_Ehi;
    __half2* L = (__half2*)g_Elo;
    H[i4 * 2] = __halves2half2(h0, h1);
    H[i4 * 2 + 1] = __halves2half2(h2, h3);
    L[i4 * 2] = __halves2half2(__float2half_rn(l0), __float2half_rn(l1));
    L[i4 * 2 + 1] = __halves2half2(__float2half_rn(l2), __float2half_rn(l3));
}

// ---------------- smem layout (bytes) ----------------
#define ROWB 144                               // 72 fp16 per row: conflict-free ldmatrix
#define SM_XHI 0                               // 128 * 144 = 18432
#define SM_EB  (TM * ROWB)                     // 18432
#define EBUF_SPLIT (64 * ROWB)                 // 9216 (one split: 64 codes)
#define EBUF_FULL (2 * EBUF_SPLIT)             // 18432 (hi + lo)
#define SM_ESQ (SM_EB + 2 * EBUF_FULL)         // 55296
#define SM_RED (SM_ESQ + KC * 4)               // 59392
#define SM_TOTB (SM_RED + TM * 12)             // 60928

// ---------------- main kernel ----------------
extern "C" __global__ void __launch_bounds__(NT, 2)
vq_main_mma(const float* __restrict__ X, const float* __restrict__ E,
            float* __restrict__ oZ, float* __restrict__ oArg, float* __restrict__ oMin) {
    extern __shared__ char sm[];
    __half* Xhi = (__half*)(sm + SM_XHI);
    float* esq_s = (float*)(sm + SM_ESQ);
    float* rbest = (float*)(sm + SM_RED);
    float* rsec = rbest + TM;
    int* ridx = (int*)(rsec + TM);

    const int tid = threadIdx.x;
    const int wid = tid >> 5, lane = tid & 31;
    const int g = lane >> 2, c4 = lane & 3;
    const int rowb = wid * 16;
    const uint32_t sbase = smem_u32(sm);

    for (int i = tid; i < KC; i += NT) esq_s[i] = g_esq[i];

    // X tile: load fp32, keep fp16-hi only (lo term folded into rescue margin)
    const float4* Xg4 = (const float4*)(X + (size_t)blockIdx.x * TM * DC);
#pragma unroll
    for (int j = 0; j < 8; j++) {
        int i4 = tid + NT * j;
        float4 v = Xg4[i4];
        int row = i4 >> 4, col = (i4 & 15) * 4;
        __half2* dst = (__half2*)(Xhi + row * 72 + col);
        dst[0] = __halves2half2(__float2half_rn(v.x), __float2half_rn(v.y));
        dst[1] = __halves2half2(__float2half_rn(v.z), __float2half_rn(v.w));
    }
    __syncthreads();

    // A fragments (fp16 hi) held in registers for the whole kernel
    uint32_t ah[4][4];
#pragma unroll
    for (int k = 0; k < 4; k++) {
        int cb = k * 16 + c4 * 2;
        ah[k][0] = *(const uint32_t*)(Xhi + (rowb + g) * 72 + cb);
        ah[k][1] = *(const uint32_t*)(Xhi + (rowb + 8 + g) * 72 + cb);
        ah[k][2] = *(const uint32_t*)(Xhi + (rowb + g) * 72 + cb + 8);
        ah[k][3] = *(const uint32_t*)(Xhi + (rowb + 8 + g) * 72 + cb + 8);
    }

    // E chunk copy (64 codes, hi+lo) into buffer b
#define COPY_E(ch, b) do {                                                        \
        const uint4* shh = (const uint4*)g_Ehi + (ch) * 512;                      \
        const uint4* sll = (const uint4*)g_Elo + (ch) * 512;                      \
        char* dst = sm + SM_EB + (b) * EBUF_FULL;                                 \
        _Pragma("unroll")                                                          \
        for (int j = 0; j < 2; j++) {                                             \
            int q = tid + NT * j;                                                 \
            int code = q >> 3, cc = q & 7;                                        \
            *(uint4*)(dst + code * ROWB + cc * 16) = shh[q];                      \
            *(uint4*)(dst + EBUF_SPLIT + code * ROWB + cc * 16) = sll[q];         \
        }                                                                          \
    } while (0)

    COPY_E(0, 0);

    float best[2], sec[2];
    int idx[2];
#pragma unroll
    for (int s = 0; s < 2; s++) { best[s] = 3.4e38f; sec[s] = 3.4e38f; idx[s] = 0; }
    __syncthreads();

    const uint32_t lrow = (lane & 7) * ROWB;                       // ldmatrix row addr part
    const uint32_t ldb = ((lane >> 4) & 1) * 32 + ((lane >> 3) & 1) * 16;  // mat -> d bytes

    for (int ch = 0; ch < 16; ch++) {
        if (ch < 15) COPY_E(ch + 1, (ch + 1) & 1);
        const uint32_t ebh = sbase + SM_EB + (ch & 1) * EBUF_FULL;
        const uint32_t ebl = ebh + EBUF_SPLIT;

        float acc[8][4];
#pragma unroll
        for (int nt = 0; nt < 8; nt++)
#pragma unroll
            for (int r = 0; r < 4; r++) acc[nt][r] = 0.f;

#pragma unroll
        for (int nt = 0; nt < 8; nt++) {
            uint32_t roff = nt * (8 * ROWB) + lrow + ldb;
            uint32_t h0, h1, h2, h3, h4, h5, h6, h7;
            uint32_t l0, l1, l2, l3, l4, l5, l6, l7;
            ldsm4(h0, h1, h2, h3, ebh + roff);        // k0, k1 (hi)
            ldsm4(h4, h5, h6, h7, ebh + roff + 64);   // k2, k3 (hi)
            ldsm4(l0, l1, l2, l3, ebl + roff);        // k0, k1 (lo)
            ldsm4(l4, l5, l6, l7, ebl + roff + 64);   // k2, k3 (lo)
            float* a = acc[nt];
            mma16816(a, ah[0][0], ah[0][1], ah[0][2], ah[0][3], h0, h1);
            mma16816(a, ah[1][0], ah[1][1], ah[1][2], ah[1][3], h2, h3);
            mma16816(a, ah[2][0], ah[2][1], ah[2][2], ah[2][3], h4, h5);
            mma16816(a, ah[3][0], ah[3][1], ah[3][2], ah[3][3], h6, h7);
            mma16816(a, ah[0][0], ah[0][1], ah[0][2], ah[0][3], l0, l1);
            mma16816(a, ah[1][0], ah[1][1], ah[1][2], ah[1][3], l2, l3);
            mma16816(a, ah[2][0], ah[2][1], ah[2][2], ah[2][3], l4, l5);
            mma16816(a, ah[3][0], ah[3][1], ah[3][2], ah[3][3], l6, l7);
        }

        // chunk epilogue: dist-without-xsq = esq - 2*dot
#pragma unroll
        for (int nt = 0; nt < 8; nt++) {
            int c0 = ch * 64 + nt * 8 + c4 * 2;
            float e0 = esq_s[c0], e1 = esq_s[c0 + 1];
            float d0 = fmaf(-2.f, acc[nt][0], e0);
            float d1 = fmaf(-2.f, acc[nt][1], e1);
            float d2 = fmaf(-2.f, acc[nt][2], e0);
            float d3 = fmaf(-2.f, acc[nt][3], e1);
            if (d0 < best[0]) { sec[0] = best[0]; best[0] = d0; idx[0] = c0; }
            else if (d0 < sec[0]) sec[0] = d0;
            if (d1 < best[0]) { sec[0] = best[0]; best[0] = d1; idx[0] = c0 + 1; }
            else if (d1 < sec[0]) sec[0] = d1;
            if (d2 < best[1]) { sec[1] = best[1]; best[1] = d2; idx[1] = c0; }
            else if (d2 < sec[1]) sec[1] = d2;
            if (d3 < best[1]) { sec[1] = best[1]; best[1] = d3; idx[1] = c0 + 1; }
            else if (d3 < sec[1]) sec[1] = d3;
        }
        __syncthreads();
    }

    // merge across the 4 lanes of each quad (same row, c4 = 0..3)
#pragma unroll
    for (int s = 0; s < 2; s++) {
#pragma unroll
        for (int o = 1; o < 4; o <<= 1) {
            float ob = __shfl_xor_sync(0xffffffffu, best[s], o);
            float os = __shfl_xor_sync(0xffffffffu, sec[s], o);
            int oi = __shfl_xor_sync(0xffffffffu, idx[s], o);
            if (ob < best[s] || (ob == best[s] && oi < idx[s])) {
                sec[s] = fminf(fminf(sec[s], os), best[s]);
                best[s] = ob; idx[s] = oi;
            } else {
                sec[s] = fminf(fminf(sec[s], os), ob);
            }
        }
        int row = rowb + s * 8 + g;
        if (c4 == 0) { rbest[row] = best[s]; rsec[row] = sec[s]; ridx[row] = idx[s]; }
    }
    __syncthreads();

    if (tid < TM) {
        // per-row state (thread = row)
        float bd = rbest[tid], sd = rsec[tid];
        int bi = ridx[tid];

        // deterministic exact-fp32 rescue for ambiguous rows
        // (threshold 0.04 >> 10 sigma of the fp16-2-product error difference)
        bool flagged = (sd - bd < 0.04f);
        unsigned fl = __ballot_sync(0xffffffffu, flagged);
        while (fl) {
            int fr = __ffs(fl) - 1; fl &= fl - 1;
            int rr = wid * 32 + fr;
            const float4* xrr = (const float4*)(X + ((size_t)blockIdx.x * TM + rr) * DC);
            float xv[64];
#pragma unroll
            for (int q = 0; q < 16; q++) {
                float4 v = xrr[q];
                xv[4 * q] = v.x; xv[4 * q + 1] = v.y;
                xv[4 * q + 2] = v.z; xv[4 * q + 3] = v.w;
            }
            float bb = 3.4e38f; int bj = 0;
            for (int c = lane; c < KC; c += 32) {
                const float4* er = (const float4*)(E + (size_t)c * DC);
                float dot = 0.f;
#pragma unroll
                for (int q = 0; q < 16; q++) {
                    float4 e4 = er[q];
                    dot = fmaf(xv[4 * q], e4.x, dot);
                    dot = fmaf(xv[4 * q + 1], e4.y, dot);
                    dot = fmaf(xv[4 * q + 2], e4.z, dot);
                    dot = fmaf(xv[4 * q + 3], e4.w, dot);
                }
                float pd = fmaf(-2.f, dot, esq_s[c]);
                if (pd < bb) { bb = pd; bj = c; }
            }
#pragma unroll
            for (int o = 16; o > 0; o >>= 1) {
                float ov = __shfl_xor_sync(0xffffffffu, bb, o);
                int oi = __shfl_xor_sync(0xffffffffu, bj, o);
                if (ov < bb || (ov == bb && oi < bj)) { bb = ov; bj = oi; }
            }
            if (lane == fr) { bd = bb; bi = bj; }
        }

        // writeout (thread = row), exact X from gmem
        size_t gr = (size_t)blockIdx.x * TM + tid;
        const float4* xr = (const float4*)(X + gr * DC);
        const float4* er = (const float4*)(E + (size_t)bi * DC);
        float4* Zr = (float4*)(oZ + gr * DC);
        float xsq = 0.f, lsum = 0.f;
        atomicAdd(&g_counts[bi], 1.0f);
        float* srow = &g_sums[bi * DC];
#pragma unroll
        for (int q = 0; q < 16; q++) {
            float4 xv4 = xr[q];
            float4 e4 = er[q];
            float d0 = e4.x - xv4.x, d1 = e4.y - xv4.y;
            float d2 = e4.z - xv4.z, d3 = e4.w - xv4.w;
            float4 z;
            z.x = xv4.x + d0; z.y = xv4.y + d1; z.z = xv4.z + d2; z.w = xv4.w + d3;
            Zr[q] = z;
            lsum = fmaf(d0, d0, lsum); lsum = fmaf(d1, d1, lsum);
            lsum = fmaf(d2, d2, lsum); lsum = fmaf(d3, d3, lsum);
            xsq = fmaf(xv4.x, xv4.x, xsq); xsq = fmaf(xv4.y, xv4.y, xsq);
            xsq = fmaf(xv4.z, xv4.z, xsq); xsq = fmaf(xv4.w, xv4.w, xsq);
            atomicAdd(srow + 4 * q + 0, xv4.x);
            atomicAdd(srow + 4 * q + 1, xv4.y);
            atomicAdd(srow + 4 * q + 2, xv4.z);
            atomicAdd(srow + 4 * q + 3, xv4.w);
        }
        oMin[gr] = xsq + bd;
        oArg[gr] = (float)bi;
#pragma unroll
        for (int o = 16; o > 0; o >>= 1) lsum += __shfl_xor_sync(0xffffffffu, lsum, o);
        if (lane == 0) atomicAdd(g_loss, lsum);
    }
}

// ---------------- finalize ----------------
__global__ void vq_fin1(const float* __restrict__ cs_in,
                        float* __restrict__ oCs, float* __restrict__ oLoss) {
    __shared__ float wsum[32];
    __shared__ float Ssh;
    int k = threadIdx.x;
    const float G = 0.99f;
    const float OMG = (float)(1.0 - 0.99);
    float c = G * cs_in[k] + OMG * g_counts[k];

    float s = c;
#pragma unroll
    for (int o = 16; o > 0; o >>= 1) s += __shfl_xor_sync(0xffffffffu, s, o);
    if ((k & 31) == 0) wsum[k >> 5] = s;
    __syncthreads();
    if (k < 32) {
        float t = wsum[k];
#pragma unroll
        for (int o = 16; o > 0; o >>= 1) t += __shfl_xor_sync(0xffffffffu, t, o);
        if (k == 0) Ssh = t;
    }
    __syncthreads();
    float S = Ssh;

    float csa = (c + 1e-9f) / (1.0f + (float)(1e-9 * 1024.0) / S);
    oCs[k] = csa;
    g_csa[k] = csa;
    if (k == 0) oLoss[0] = 0.25f * g_loss[0] / (float)NV;
}

// oEn/oMa offset by +1 float in d_out -> scalar stores only
__global__ void vq_fin2(const float* __restrict__ mavg,
                        float* __restrict__ oEn, float* __restrict__ oMa) {
    const float G = 0.99f;
    const float OMG = (float)(1.0 - 0.99);
    int i4 = blockIdx.x * blockDim.x + threadIdx.x;
    float4 mv = ((const float4*)mavg)[i4];
    float4 sv = ((const float4*)g_sums)[i4];
    float csa = g_csa[i4 >> 4];
    int b = i4 * 4;
    float m0 = G * mv.x + OMG * sv.x;
    float m1 = G * mv.y + OMG * sv.y;
    float m2 = G * mv.z + OMG * sv.z;
    float m3 = G * mv.w + OMG * sv.w;
    oMa[b + 0] = m0;  oEn[b + 0] = m0 / csa;
    oMa[b + 1] = m1;  oEn[b + 1] = m1 / csa;
    oMa[b + 2] = m2;  oEn[b + 2] = m2 / csa;
    oMa[b + 3] = m3;  oEn[b + 3] = m3 / csa;
}

// ---------------- launch ----------------
extern "C" void kernel_launch(void* const* d_in, const int* in_sizes, int n_in,
                              void* d_out, int out_size) {
    const float* X  = (const float*)d_in[0];
    const float* E  = (const float*)d_in[1];
    const float* cs = (const float*)d_in[2];
    const float* ma = (const float*)d_in[3];

    float* o = (float*)d_out;
    float* oZ    = o;
    float* oLoss = o + (size_t)NV * DC;
    float* oArg  = oLoss + 1;
    float* oMin  = oArg + NV;
    float* oEn   = oMin + NV;
    float* oCs   = oEn + (size_t)KC * DC;
    float* oMa   = oCs + KC;

    cudaFuncSetAttribute(vq_main_mma, cudaFuncAttributeMaxDynamicSharedMemorySize, SM_TOTB);

    vq_zero<<<(KC * DC / 4 + KC + 1 + 255) / 256, 256>>>();
    vq_esq<<<(KC + 255) / 256, 256>>>(E);
    vq_esplit<<<KC * DC / 4 / 256, 256>>>(E);
    vq_main_mma<<<NV / TM, NT, SM_TOTB>>>(X, E, oZ, oArg, oMin);
    vq_fin1<<<1, KC>>>(cs, oCs, oLoss);
    vq_fin2<<<KC * DC / 4 / 256, 256>>>(ma, oEn, oMa);
}

// round 11
// speedup vs baseline: 2.4455x; 1.1429x over previous
#include <cuda_runtime.h>
#include <cuda_fp16.h>
#include <cstdint>

#define KC 1024
#define DC 64
#define NV 131072
#define TM 128      // rows per CTA
#define NT 256      // threads (8 warps x 16 rows)

// ---------------- scratch ----------------
__device__ __align__(16) float g_esq[KC];
__device__ __align__(16) float g_counts[KC];
__device__ __align__(16) float g_sums[KC * DC];
__device__ float g_loss[1];
__device__ __align__(16) float g_csa[KC];
__device__ __align__(16) __half g_Ehi[KC * DC];   // NEGATED e hi
__device__ __align__(16) __half g_Elo[KC * DC];   // NEGATED e lo

// ---------------- PTX helpers (arch-neutral) ----------------
__device__ __forceinline__ void mma16816(float* a,
                                         uint32_t a0, uint32_t a1, uint32_t a2, uint32_t a3,
                                         uint32_t b0, uint32_t b1) {
    asm volatile("mma.sync.aligned.m16n8k16.row.col.f32.f16.f16.f32 "
                 "{%0,%1,%2,%3}, {%4,%5,%6,%7}, {%8,%9}, {%0,%1,%2,%3};"
                 : "+f"(a[0]), "+f"(a[1]), "+f"(a[2]), "+f"(a[3])
                 : "r"(a0), "r"(a1), "r"(a2), "r"(a3), "r"(b0), "r"(b1));
}
__device__ __forceinline__ void ldsm4(uint32_t& r0, uint32_t& r1, uint32_t& r2, uint32_t& r3,
                                      uint32_t addr) {
    asm volatile("ldmatrix.sync.aligned.m8n8.x4.shared.b16 {%0,%1,%2,%3}, [%4];"
                 : "=r"(r0), "=r"(r1), "=r"(r2), "=r"(r3) : "r"(addr));
}
__device__ __forceinline__ uint32_t smem_u32(const void* p) {
    uint32_t a;
    asm("{ .reg .u64 t; cvta.to.shared.u64 t, %1; cvt.u32.u64 %0, t; }" : "=r"(a) : "l"(p));
    return a;
}

// ---------------- prep kernels ----------------
__global__ void vq_zero() {
    int i = blockIdx.x * blockDim.x + threadIdx.x;
    if (i < KC * DC / 4) {
        ((float4*)g_sums)[i] = make_float4(0.f, 0.f, 0.f, 0.f);
    } else if (i < KC * DC / 4 + KC) {
        g_counts[i - KC * DC / 4] = 0.f;
    } else if (i == KC * DC / 4 + KC) {
        g_loss[0] = 0.f;
    }
}

__global__ void vq_esq(const float* __restrict__ E) {
    int k = blockIdx.x * blockDim.x + threadIdx.x;
    if (k < KC) {
        const float4* r = (const float4*)(E + (size_t)k * DC);
        float s = 0.f;
#pragma unroll
        for (int q = 0; q < DC / 4; q++) {
            float4 v = r[q];
            s = fmaf(v.x, v.x, s); s = fmaf(v.y, v.y, s);
            s = fmaf(v.z, v.z, s); s = fmaf(v.w, v.w, s);
        }
        g_esq[k] = s;
    }
}

// split NEGATED E into fp16 hi/lo (so MMA accumulates -dot on top of esq/2 init)
__global__ void vq_esplit(const float* __restrict__ E) {
    int i4 = blockIdx.x * blockDim.x + threadIdx.x;   // < KC*DC/4
    float4 v = ((const float4*)E)[i4];
    float n0 = -v.x, n1 = -v.y, n2 = -v.z, n3 = -v.w;
    __half h0 = __float2half_rn(n0), h1 = __float2half_rn(n1);
    __half h2 = __float2half_rn(n2), h3 = __float2half_rn(n3);
    float l0 = n0 - __half2float(h0), l1 = n1 - __half2float(h1);
    float l2 = n2 - __half2float(h2), l3 = n3 - __half2float(h3);
    __half2* H = (__half2*)g_Ehi;
    __half2* L = (__half2*)g_Elo;
    H[i4 * 2] = __halves2half2(h0, h1);
    H[i4 * 2 + 1] = __halves2half2(h2, h3);
    L[i4 * 2] = __halves2half2(__float2half_rn(l0), __float2half_rn(l1));
    L[i4 * 2 + 1] = __halves2half2(__float2half_rn(l2), __float2half_rn(l3));
}

// ---------------- smem layout (bytes) ----------------
#define ROWB 144                               // 72 fp16 per row: conflict-free ldmatrix
#define SM_XHI 0                               // 128 * 144 = 18432
#define SM_EB  (TM * ROWB)                     // 18432
#define EBUF_SPLIT (64 * ROWB)                 // 9216 (one split: 64 codes)
#define EBUF_FULL (2 * EBUF_SPLIT)             // 18432 (hi + lo)
#define SM_ESQ (SM_EB + 2 * EBUF_FULL)         // 55296   esq*0.5 per code
#define SM_RED (SM_ESQ + KC * 4)               // 59392
#define SM_TOTB (SM_RED + TM * 12)             // 60928

// ---------------- main kernel ----------------
extern "C" __global__ void __launch_bounds__(NT, 2)
vq_main_mma(const float* __restrict__ X, const float* __restrict__ E,
            float* __restrict__ oZ, float* __restrict__ oArg, float* __restrict__ oMin) {
    extern __shared__ char sm[];
    __half* Xhi = (__half*)(sm + SM_XHI);
    float* esq2_s = (float*)(sm + SM_ESQ);    // esq * 0.5
    float* rbest = (float*)(sm + SM_RED);
    float* rsec = rbest + TM;
    int* ridx = (int*)(rsec + TM);

    const int tid = threadIdx.x;
    const int wid = tid >> 5, lane = tid & 31;
    const int g = lane >> 2, c4 = lane & 3;
    const int rowb = wid * 16;
    const uint32_t sbase = smem_u32(sm);

    for (int i = tid; i < KC; i += NT) esq2_s[i] = 0.5f * g_esq[i];

    // X tile: load fp32, keep fp16-hi only (lo term folded into rescue margin)
    const float4* Xg4 = (const float4*)(X + (size_t)blockIdx.x * TM * DC);
#pragma unroll
    for (int j = 0; j < 8; j++) {
        int i4 = tid + NT * j;
        float4 v = Xg4[i4];
        int row = i4 >> 4, col = (i4 & 15) * 4;
        __half2* dst = (__half2*)(Xhi + row * 72 + col);
        dst[0] = __halves2half2(__float2half_rn(v.x), __float2half_rn(v.y));
        dst[1] = __halves2half2(__float2half_rn(v.z), __float2half_rn(v.w));
    }
    __syncthreads();

    // A fragments (fp16 hi) held in registers for the whole kernel
    uint32_t ah[4][4];
#pragma unroll
    for (int k = 0; k < 4; k++) {
        int cb = k * 16 + c4 * 2;
        ah[k][0] = *(const uint32_t*)(Xhi + (rowb + g) * 72 + cb);
        ah[k][1] = *(const uint32_t*)(Xhi + (rowb + 8 + g) * 72 + cb);
        ah[k][2] = *(const uint32_t*)(Xhi + (rowb + g) * 72 + cb + 8);
        ah[k][3] = *(const uint32_t*)(Xhi + (rowb + 8 + g) * 72 + cb + 8);
    }

    // E chunk copy (64 codes, hi+lo) into buffer b
#define COPY_E(ch, b) do {                                                        \
        const uint4* shh = (const uint4*)g_Ehi + (ch) * 512;                      \
        const uint4* sll = (const uint4*)g_Elo + (ch) * 512;                      \
        char* dst = sm + SM_EB + (b) * EBUF_FULL;                                 \
        _Pragma("unroll")                                                          \
        for (int j = 0; j < 2; j++) {                                             \
            int q = tid + NT * j;                                                 \
            int code = q >> 3, cc = q & 7;                                        \
            *(uint4*)(dst + code * ROWB + cc * 16) = shh[q];                      \
            *(uint4*)(dst + EBUF_SPLIT + code * ROWB + cc * 16) = sll[q];         \
        }                                                                          \
    } while (0)

    COPY_E(0, 0);

    // best/sec tracked in HALF-dist units (acc = esq/2 - dot = dist/2)
    float best[2], sec[2];
    int idx[2];
#pragma unroll
    for (int s = 0; s < 2; s++) { best[s] = 3.4e38f; sec[s] = 3.4e38f; idx[s] = 0; }
    __syncthreads();

    const uint32_t lrow = (lane & 7) * ROWB;                       // ldmatrix row addr part
    const uint32_t ldb = ((lane >> 4) & 1) * 32 + ((lane >> 3) & 1) * 16;  // mat -> d bytes

    for (int ch = 0; ch < 16; ch++) {
        if (ch < 15) COPY_E(ch + 1, (ch + 1) & 1);
        const uint32_t ebh = sbase + SM_EB + (ch & 1) * EBUF_FULL;
        const uint32_t ebl = ebh + EBUF_SPLIT;

        // init acc with esq/2 (esq folded into GEMM; E is negated)
        float acc[8][4];
#pragma unroll
        for (int nt = 0; nt < 8; nt++) {
            float2 p = *(const float2*)(esq2_s + ch * 64 + nt * 8 + c4 * 2);
            acc[nt][0] = p.x; acc[nt][1] = p.y;
            acc[nt][2] = p.x; acc[nt][3] = p.y;
        }

#pragma unroll
        for (int nt = 0; nt < 8; nt++) {
            uint32_t roff = nt * (8 * ROWB) + lrow + ldb;
            uint32_t h0, h1, h2, h3, h4, h5, h6, h7;
            uint32_t l0, l1, l2, l3, l4, l5, l6, l7;
            ldsm4(h0, h1, h2, h3, ebh + roff);        // k0, k1 (hi)
            ldsm4(h4, h5, h6, h7, ebh + roff + 64);   // k2, k3 (hi)
            ldsm4(l0, l1, l2, l3, ebl + roff);        // k0, k1 (lo)
            ldsm4(l4, l5, l6, l7, ebl + roff + 64);   // k2, k3 (lo)
            float* a = acc[nt];
            mma16816(a, ah[0][0], ah[0][1], ah[0][2], ah[0][3], h0, h1);
            mma16816(a, ah[1][0], ah[1][1], ah[1][2], ah[1][3], h2, h3);
            mma16816(a, ah[2][0], ah[2][1], ah[2][2], ah[2][3], h4, h5);
            mma16816(a, ah[3][0], ah[3][1], ah[3][2], ah[3][3], h6, h7);
            mma16816(a, ah[0][0], ah[0][1], ah[0][2], ah[0][3], l0, l1);
            mma16816(a, ah[1][0], ah[1][1], ah[1][2], ah[1][3], l2, l3);
            mma16816(a, ah[2][0], ah[2][1], ah[2][2], ah[2][3], l4, l5);
            mma16816(a, ah[3][0], ah[3][1], ah[3][2], ah[3][3], l6, l7);
        }

        // chunk epilogue: acc IS dist/2; branchless min/argmin (5 fixed-lat instrs/value)
#pragma unroll
        for (int nt = 0; nt < 8; nt++) {
            int c0 = ch * 64 + nt * 8 + c4 * 2;
            float d0 = acc[nt][0], d1 = acc[nt][1];
            float d2 = acc[nt][2], d3 = acc[nt][3];
            sec[0] = fminf(sec[0], fmaxf(best[0], d0));
            idx[0] = (d0 < best[0]) ? c0 : idx[0];
            best[0] = fminf(best[0], d0);
            sec[0] = fminf(sec[0], fmaxf(best[0], d1));
            idx[0] = (d1 < best[0]) ? (c0 + 1) : idx[0];
            best[0] = fminf(best[0], d1);
            sec[1] = fminf(sec[1], fmaxf(best[1], d2));
            idx[1] = (d2 < best[1]) ? c0 : idx[1];
            best[1] = fminf(best[1], d2);
            sec[1] = fminf(sec[1], fmaxf(best[1], d3));
            idx[1] = (d3 < best[1]) ? (c0 + 1) : idx[1];
            best[1] = fminf(best[1], d3);
        }
        __syncthreads();
    }

    // merge across the 4 lanes of each quad (same row, c4 = 0..3)
#pragma unroll
    for (int s = 0; s < 2; s++) {
#pragma unroll
        for (int o = 1; o < 4; o <<= 1) {
            float ob = __shfl_xor_sync(0xffffffffu, best[s], o);
            float os = __shfl_xor_sync(0xffffffffu, sec[s], o);
            int oi = __shfl_xor_sync(0xffffffffu, idx[s], o);
            if (ob < best[s] || (ob == best[s] && oi < idx[s])) {
                sec[s] = fminf(fminf(sec[s], os), best[s]);
                best[s] = ob; idx[s] = oi;
            } else {
                sec[s] = fminf(fminf(sec[s], os), ob);
            }
        }
        int row = rowb + s * 8 + g;
        if (c4 == 0) { rbest[row] = best[s]; rsec[row] = sec[s]; ridx[row] = idx[s]; }
    }
    __syncthreads();

    if (tid < TM) {
        // per-row state (thread = row); convert half-dist -> dist units
        float bd = 2.f * rbest[tid], sd = 2.f * rsec[tid];
        int bi = ridx[tid];

        // deterministic exact-fp32 rescue for ambiguous rows
        bool flagged = (sd - bd < 0.04f);
        unsigned fl = __ballot_sync(0xffffffffu, flagged);
        while (fl) {
            int fr = __ffs(fl) - 1; fl &= fl - 1;
            int rr = wid * 32 + fr;
            const float4* xrr = (const float4*)(X + ((size_t)blockIdx.x * TM + rr) * DC);
            float xv[64];
#pragma unroll
            for (int q = 0; q < 16; q++) {
                float4 v = xrr[q];
                xv[4 * q] = v.x; xv[4 * q + 1] = v.y;
                xv[4 * q + 2] = v.z; xv[4 * q + 3] = v.w;
            }
            float bb = 3.4e38f; int bj = 0;
            for (int c = lane; c < KC; c += 32) {
                const float4* er = (const float4*)(E + (size_t)c * DC);
                float dot = 0.f;
#pragma unroll
                for (int q = 0; q < 16; q++) {
                    float4 e4 = er[q];
                    dot = fmaf(xv[4 * q], e4.x, dot);
                    dot = fmaf(xv[4 * q + 1], e4.y, dot);
                    dot = fmaf(xv[4 * q + 2], e4.z, dot);
                    dot = fmaf(xv[4 * q + 3], e4.w, dot);
                }
                float pd = fmaf(-2.f, dot, 2.f * esq2_s[c]);
                if (pd < bb) { bb = pd; bj = c; }
            }
#pragma unroll
            for (int o = 16; o > 0; o >>= 1) {
                float ov = __shfl_xor_sync(0xffffffffu, bb, o);
                int oi = __shfl_xor_sync(0xffffffffu, bj, o);
                if (ov < bb || (ov == bb && oi < bj)) { bb = ov; bj = oi; }
            }
            if (lane == fr) { bd = bb; bi = bj; }
        }

        // writeout (thread = row), exact X from gmem
        size_t gr = (size_t)blockIdx.x * TM + tid;
        const float4* xr = (const float4*)(X + gr * DC);
        const float4* er = (const float4*)(E + (size_t)bi * DC);
        float4* Zr = (float4*)(oZ + gr * DC);
        float xsq = 0.f, lsum = 0.f;
        atomicAdd(&g_counts[bi], 1.0f);
        float* srow = &g_sums[bi * DC];
#pragma unroll
        for (int q = 0; q < 16; q++) {
            float4 xv4 = xr[q];
            float4 e4 = er[q];
            float d0 = e4.x - xv4.x, d1 = e4.y - xv4.y;
            float d2 = e4.z - xv4.z, d3 = e4.w - xv4.w;
            float4 z;
            z.x = xv4.x + d0; z.y = xv4.y + d1; z.z = xv4.z + d2; z.w = xv4.w + d3;
            Zr[q] = z;
            lsum = fmaf(d0, d0, lsum); lsum = fmaf(d1, d1, lsum);
            lsum = fmaf(d2, d2, lsum); lsum = fmaf(d3, d3, lsum);
            xsq = fmaf(xv4.x, xv4.x, xsq); xsq = fmaf(xv4.y, xv4.y, xsq);
            xsq = fmaf(xv4.z, xv4.z, xsq); xsq = fmaf(xv4.w, xv4.w, xsq);
            atomicAdd(srow + 4 * q + 0, xv4.x);
            atomicAdd(srow + 4 * q + 1, xv4.y);
            atomicAdd(srow + 4 * q + 2, xv4.z);
            atomicAdd(srow + 4 * q + 3, xv4.w);
        }
        oMin[gr] = xsq + bd;
        oArg[gr] = (float)bi;
#pragma unroll
        for (int o = 16; o > 0; o >>= 1) lsum += __shfl_xor_sync(0xffffffffu, lsum, o);
        if (lane == 0) atomicAdd(g_loss, lsum);
    }
}

// ---------------- finalize ----------------
__global__ void vq_fin1(const float* __restrict__ cs_in,
                        float* __restrict__ oCs, float* __restrict__ oLoss) {
    __shared__ float wsum[32];
    __shared__ float Ssh;
    int k = threadIdx.x;
    const float G = 0.99f;
    const float OMG = (float)(1.0 - 0.99);
    float c = G * cs_in[k] + OMG * g_counts[k];

    float s = c;
#pragma unroll
    for (int o = 16; o > 0; o >>= 1) s += __shfl_xor_sync(0xffffffffu, s, o);
    if ((k & 31) == 0) wsum[k >> 5] = s;
    __syncthreads();
    if (k < 32) {
        float t = wsum[k];
#pragma unroll
        for (int o = 16; o > 0; o >>= 1) t += __shfl_xor_sync(0xffffffffu, t, o);
        if (k == 0) Ssh = t;
    }
    __syncthreads();
    float S = Ssh;

    float csa = (c + 1e-9f) / (1.0f + (float)(1e-9 * 1024.0) / S);
    oCs[k] = csa;
    g_csa[k] = csa;
    if (k == 0) oLoss[0] = 0.25f * g_loss[0] / (float)NV;
}

// oEn/oMa offset by +1 float in d_out -> scalar stores only
__global__ void vq_fin2(const float* __restrict__ mavg,
                        float* __restrict__ oEn, float* __restrict__ oMa) {
    const float G = 0.99f;
    const float OMG = (float)(1.0 - 0.99);
    int i4 = blockIdx.x * blockDim.x + threadIdx.x;
    float4 mv = ((const float4*)mavg)[i4];
    float4 sv = ((const float4*)g_sums)[i4];
    float csa = g_csa[i4 >> 4];
    int b = i4 * 4;
    float m0 = G * mv.x + OMG * sv.x;
    float m1 = G * mv.y + OMG * sv.y;
    float m2 = G * mv.z + OMG * sv.z;
    float m3 = G * mv.w + OMG * sv.w;
    oMa[b + 0] = m0;  oEn[b + 0] = m0 / csa;
    oMa[b + 1] = m1;  oEn[b + 1] = m1 / csa;
    oMa[b + 2] = m2;  oEn[b + 2] = m2 / csa;
    oMa[b + 3] = m3;  oEn[b + 3] = m3 / csa;
}

// ---------------- launch ----------------
extern "C" void kernel_launch(void* const* d_in, const int* in_sizes, int n_in,
                              void* d_out, int out_size) {
    const float* X  = (const float*)d_in[0];
    const float* E  = (const float*)d_in[1];
    const float* cs = (const float*)d_in[2];
    const float* ma = (const float*)d_in[3];

    float* o = (float*)d_out;
    float* oZ    = o;
    float* oLoss = o + (size_t)NV * DC;
    float* oArg  = oLoss + 1;
    float* oMin  = oArg + NV;
    float* oEn   = oMin + NV;
    float* oCs   = oEn + (size_t)KC * DC;
    float* oMa   = oCs + KC;

    cudaFuncSetAttribute(vq_main_mma, cudaFuncAttributeMaxDynamicSharedMemorySize, SM_TOTB);

    vq_zero<<<(KC * DC / 4 + KC + 1 + 255) / 256, 256>>>();
    vq_esq<<<(KC + 255) / 256, 256>>>(E);
    vq_esplit<<<KC * DC / 4 / 256, 256>>>(E);
    vq_main_mma<<<NV / TM, NT, SM_TOTB>>>(X, E, oZ, oArg, oMin);
    vq_fin1<<<1, KC>>>(cs, oCs, oLoss);
    vq_fin2<<<KC * DC / 4 / 256, 256>>>(ma, oEn, oMa);
}